// round 10
// baseline (speedup 1.0000x reference)
#include <cuda_runtime.h>
#include <cuda_bf16.h>
#include <cstdint>

#define N_NODES 50000
#define N_EDGES 800000
#define SCAN_BLOCKS ((N_NODES + 255) / 256)   // 196
#define GEMM_ROWS 128
#define NTILES ((N_NODES + GEMM_ROWS - 1) / GEMM_ROWS)   // 391
#define GEMM_GRID 148
#define XCHUNKS (N_NODES * 32)                // 1.6M float4 chunks

// ---- scratch (device globals; no allocs) ----
__device__ __align__(16) float4 g_neigh4[N_NODES * 32];   // mean-aggregated neigh (fp32)
__device__ __align__(16) uint2  g_xbf16[N_NODES * 32];    // x rounded to bf16 (gather copy)
__device__ int g_deg_i[N_NODES];
__device__ int g_cursor[N_NODES];
__device__ int g_src_bin[N_EDGES];
__device__ int g_scan_val[SCAN_BLOCKS];
__device__ volatile int g_scan_flag[SCAN_BLOCKS];
__device__ int g_ei_is64;

__device__ __forceinline__ uint2 cvt_hi4(float4 v) {
    __nv_bfloat162 a = __floats2bfloat162_rn(v.x, v.y);
    __nv_bfloat162 b = __floats2bfloat162_rn(v.z, v.w);
    uint2 r;
    r.x = *reinterpret_cast<uint32_t*>(&a);
    r.y = *reinterpret_cast<uint32_t*>(&b);
    return r;
}
__device__ __forceinline__ uint2 cvt_lo4(float4 v) {
    __nv_bfloat162 a = __floats2bfloat162_rn(v.x, v.y);
    __nv_bfloat162 b = __floats2bfloat162_rn(v.z, v.w);
    float4 l = make_float4(v.x - __bfloat162float(a.x), v.y - __bfloat162float(a.y),
                           v.z - __bfloat162float(b.x), v.w - __bfloat162float(b.y));
    __nv_bfloat162 c = __floats2bfloat162_rn(l.x, l.y);
    __nv_bfloat162 d = __floats2bfloat162_rn(l.z, l.w);
    uint2 r;
    r.x = *reinterpret_cast<uint32_t*>(&c);
    r.y = *reinterpret_cast<uint32_t*>(&d);
    return r;
}

// ---- dtype-agnostic edge index reads (int32 loads even for int64 buffers:
//      values < 50000 so the little-endian low word is the value) ----
__device__ __forceinline__ int load_src(const long long* ei, int e) {
    const int* p = (const int*)ei;
    return g_ei_is64 ? __ldg(p + 2 * e) : __ldg(p + e);
}
__device__ __forceinline__ int load_dst(const long long* ei, int e) {
    const int* p = (const int*)ei;
    return g_ei_is64 ? __ldg(p + 2 * (N_EDGES + e)) : __ldg(p + N_EDGES + e);
}

// ===========================================================================
// K1: convert x -> bf16 gather copy, zero counters, probe dtype (one launch)
// ===========================================================================
__global__ void __launch_bounds__(256) k_prep(const long long* __restrict__ ei,
                                              const float4* __restrict__ x4) {
    int i = blockIdx.x * blockDim.x + threadIdx.x;
    if (i < XCHUNKS) g_xbf16[i] = cvt_hi4(__ldg(x4 + i));
    if (i < N_NODES) g_deg_i[i] = 0;
    if (i < SCAN_BLOCKS) g_scan_flag[i] = 0;
    if (i == 0) {
        int ok = 1;
        for (int k = 0; k < 64; k++) {
            long long v = ei[k];
            if (v < 0 || v >= N_NODES) { ok = 0; break; }
        }
        g_ei_is64 = ok;
    }
}

// ===========================================================================
// K2: in-degree histogram
// ===========================================================================
__global__ void __launch_bounds__(256) k_hist(const long long* __restrict__ ei) {
    int e = blockIdx.x * blockDim.x + threadIdx.x;
    if (e >= N_EDGES) return;
    int d = load_dst(ei, e);
    if ((unsigned)d < N_NODES) atomicAdd(&g_deg_i[d], 1);
}

// ===========================================================================
// K3: single-pass exclusive scan (full lookback; flags re-zeroed by k_prep)
// ===========================================================================
__global__ void __launch_bounds__(256) k_scan() {
    __shared__ int s[256];
    __shared__ int carry;
    const int b = blockIdx.x;
    const int tid = threadIdx.x;
    const int i = b * 256 + tid;

    int v = (i < N_NODES) ? g_deg_i[i] : 0;
    s[tid] = v;
    __syncthreads();
    int acc = v;
    #pragma unroll
    for (int off = 1; off < 256; off <<= 1) {
        int t = (tid >= off) ? s[tid - off] : 0;
        __syncthreads();
        acc += t;
        s[tid] = acc;
        __syncthreads();
    }
    if (tid == 255) {
        g_scan_val[b] = acc;
        __threadfence();
        g_scan_flag[b] = 1;
    }
    if (tid == 0) carry = 0;
    __syncthreads();

    int sum = 0;
    for (int p = tid; p < b; p += 256) {
        while (g_scan_flag[p] == 0) { }
        sum += g_scan_val[p];
    }
    if (sum) atomicAdd(&carry, sum);
    __syncthreads();

    if (i < N_NODES) g_cursor[i] = carry + (acc - v);
}

// ===========================================================================
// K4: bin fill — counting-sort src ids by dst
// ===========================================================================
__global__ void __launch_bounds__(256) k_binfill(const long long* __restrict__ ei) {
    int e = blockIdx.x * blockDim.x + threadIdx.x;
    if (e >= N_EDGES) return;
    int s = load_src(ei, e);
    int d = load_dst(ei, e);
    if ((unsigned)s >= N_NODES || (unsigned)d >= N_NODES) return;
    int pos = atomicAdd(&g_cursor[d], 1);
    g_src_bin[pos] = s;
}

// ===========================================================================
// K5: gather-aggregate over bf16 x (256B/row gather — half the L2 traffic).
// One warp per node; lane holds 4 channels (uint2 = 4 bf16), fp32 accum.
// ===========================================================================
__global__ void __launch_bounds__(256) k_aggregate() {
    int n = (blockIdx.x * blockDim.x + threadIdx.x) >> 5;
    int lane = threadIdx.x & 31;
    if (n >= N_NODES) return;

    int end = g_cursor[n];
    int deg = g_deg_i[n];
    int beg = end - deg;

    float4 a0 = make_float4(0.f, 0.f, 0.f, 0.f);
    float4 a1 = make_float4(0.f, 0.f, 0.f, 0.f);

    for (int base = beg; base < end; base += 32) {
        int m = min(32, end - base);
        int s = (base + lane < end) ? __ldg(g_src_bin + base + lane) : 0;
        int j = 0;
        for (; j + 1 < m; j += 2) {
            int s0 = __shfl_sync(0xffffffffu, s, j);
            int s1 = __shfl_sync(0xffffffffu, s, j + 1);
            uint2 u0 = g_xbf16[s0 * 32 + lane];
            uint2 u1 = g_xbf16[s1 * 32 + lane];
            float2 p0 = __bfloat1622float2(*reinterpret_cast<__nv_bfloat162*>(&u0.x));
            float2 p1 = __bfloat1622float2(*reinterpret_cast<__nv_bfloat162*>(&u0.y));
            float2 q0 = __bfloat1622float2(*reinterpret_cast<__nv_bfloat162*>(&u1.x));
            float2 q1 = __bfloat1622float2(*reinterpret_cast<__nv_bfloat162*>(&u1.y));
            a0.x += p0.x; a0.y += p0.y; a0.z += p1.x; a0.w += p1.y;
            a1.x += q0.x; a1.y += q0.y; a1.z += q1.x; a1.w += q1.y;
        }
        if (j < m) {
            int s0 = __shfl_sync(0xffffffffu, s, j);
            uint2 u0 = g_xbf16[s0 * 32 + lane];
            float2 p0 = __bfloat1622float2(*reinterpret_cast<__nv_bfloat162*>(&u0.x));
            float2 p1 = __bfloat1622float2(*reinterpret_cast<__nv_bfloat162*>(&u0.y));
            a0.x += p0.x; a0.y += p0.y; a0.z += p1.x; a0.w += p1.y;
        }
    }
    float sc = 1.0f / fmaxf((float)deg, 1.0f);
    g_neigh4[n * 32 + lane] = make_float4((a0.x + a1.x) * sc, (a0.y + a1.y) * sc,
                                          (a0.z + a1.z) * sc, (a0.w + a1.w) * sc);
}

// ===========================================================================
// K6: mma.sync bf16-split GEMM + bias + row L2-normalize (persistent).
// (unchanged from R9 — passing at rel_err 4e-6)
// ===========================================================================
#define GSTRIDE 528
#define SM_BIAS 0
#define SM_A    1024
#define SM_BHI  (SM_A   + 128 * GSTRIDE)
#define SM_BLO  (SM_BHI + 128 * GSTRIDE)
#define SM_TOT  (SM_BLO + 128 * GSTRIDE)   // 203776 B

__device__ __forceinline__ uint32_t smem_u32(const void* p) {
    uint32_t a;
    asm("{ .reg .u64 t; cvta.to.shared.u64 t, %1; cvt.u32.u64 %0, t; }" : "=r"(a) : "l"(p));
    return a;
}

__device__ __forceinline__ void ldsm_x4(uint32_t& r0, uint32_t& r1, uint32_t& r2,
                                        uint32_t& r3, uint32_t addr) {
    asm volatile("ldmatrix.sync.aligned.m8n8.x4.shared.b16 {%0,%1,%2,%3}, [%4];"
                 : "=r"(r0), "=r"(r1), "=r"(r2), "=r"(r3) : "r"(addr));
}

__device__ __forceinline__ void mma_bf16(float* c, const uint32_t* a, const uint32_t* b) {
    asm volatile(
        "mma.sync.aligned.m16n8k16.row.col.f32.bf16.bf16.f32 "
        "{%0,%1,%2,%3}, {%4,%5,%6,%7}, {%8,%9}, {%0,%1,%2,%3};"
        : "+f"(c[0]), "+f"(c[1]), "+f"(c[2]), "+f"(c[3])
        : "r"(a[0]), "r"(a[1]), "r"(a[2]), "r"(a[3]), "r"(b[0]), "r"(b[1]));
}

// one bf16 pass: C += A_warp_tile(16xK) @ B_tile(128xK)^T  -> 16x128
__device__ __forceinline__ void run_pass(uint32_t aA, const uint32_t* bA,
                                         float (*c)[4]) {
    #pragma unroll 4
    for (int k = 0; k < 16; k++) {
        uint32_t a[4], b[16][2];
        ldsm_x4(a[0], a[1], a[2], a[3], aA + k * 32);
        #pragma unroll
        for (int p = 0; p < 8; p++)
            ldsm_x4(b[2*p][0], b[2*p][1], b[2*p+1][0], b[2*p+1][1], bA[p] + k * 32);
        #pragma unroll
        for (int nt = 0; nt < 16; nt++)
            mma_bf16(c[nt], a, b[nt]);
    }
}

__global__ void __launch_bounds__(256, 1) gemm_norm_kernel(
    const float4* __restrict__ x4,
    const float4* __restrict__ W4,     // [128][64] float4 (W[c][k])
    const float*  __restrict__ bias,   // [128]
    float4*       __restrict__ out4)   // [N_NODES][32]
{
    extern __shared__ char smem[];
    const uint32_t sb = smem_u32(smem);
    const int tid  = threadIdx.x;
    const int lane = tid & 31;
    const int wid  = tid >> 5;      // warp w -> rows w*16..+15, all 128 cols

    for (int i = tid; i < 8192; i += 256) {
        int c = i >> 6, k4 = i & 63;
        float4 v = __ldg(W4 + i);
        uint32_t off = (uint32_t)(c * GSTRIDE + k4 * 8);
        *reinterpret_cast<uint2*>(smem + SM_BHI + off) = cvt_hi4(v);
        *reinterpret_cast<uint2*>(smem + SM_BLO + off) = cvt_lo4(v);
    }
    if (tid < 128) ((float*)(smem + SM_BIAS))[tid] = __ldg(bias + tid);
    __syncthreads();

    const int q = lane >> 3, r = lane & 7;
    const uint32_t aRel = (uint32_t)((wid * 16 + (q & 1) * 8 + r) * GSTRIDE + (q >> 1) * 16);
    uint32_t bRel[8];
    #pragma unroll
    for (int p = 0; p < 8; p++)
        bRel[p] = (uint32_t)((p * 16 + (q >> 1) * 8 + r) * GSTRIDE + (q & 1) * 16);

    float2* out2 = (float2*)out4;
    const float* bs = (const float*)(smem + SM_BIAS);

    for (int tile = blockIdx.x; tile < NTILES; tile += GEMM_GRID) {
        const int base = tile * GEMM_ROWS;

        for (int i = tid; i < 8192; i += 256) {
            int rr = i >> 6, k4 = i & 63;
            int row = base + rr;
            float4 v = make_float4(0.f, 0.f, 0.f, 0.f);
            if (row < N_NODES)
                v = (k4 < 32) ? __ldg(x4 + row * 32 + k4)
                              : g_neigh4[row * 32 + (k4 - 32)];
            *reinterpret_cast<uint2*>(smem + SM_A + rr * GSTRIDE + k4 * 8) = cvt_hi4(v);
        }
        __syncthreads();

        float c[16][4];
        #pragma unroll
        for (int nt = 0; nt < 16; nt++)
            #pragma unroll
            for (int j = 0; j < 4; j++) c[nt][j] = 0.f;

        uint32_t bHi[8], bLo[8];
        #pragma unroll
        for (int p = 0; p < 8; p++) {
            bHi[p] = sb + SM_BHI + bRel[p];
            bLo[p] = sb + SM_BLO + bRel[p];
        }

        run_pass(sb + SM_A + aRel, bHi, c);
        run_pass(sb + SM_A + aRel, bLo, c);
        __syncthreads();

        for (int i = tid; i < 8192; i += 256) {
            int rr = i >> 6, k4 = i & 63;
            int row = base + rr;
            float4 v = make_float4(0.f, 0.f, 0.f, 0.f);
            if (row < N_NODES)
                v = (k4 < 32) ? __ldg(x4 + row * 32 + k4)
                              : g_neigh4[row * 32 + (k4 - 32)];
            *reinterpret_cast<uint2*>(smem + SM_A + rr * GSTRIDE + k4 * 8) = cvt_lo4(v);
        }
        __syncthreads();

        run_pass(sb + SM_A + aRel, bHi, c);

        #pragma unroll
        for (int h = 0; h < 2; h++) {
            float o0[16], o1[16];
            float ss = 0.f;
            #pragma unroll
            for (int nt = 0; nt < 16; nt++) {
                int col = nt * 8 + (lane & 3) * 2;
                float v0 = c[nt][2*h + 0] + bs[col + 0];
                float v1 = c[nt][2*h + 1] + bs[col + 1];
                o0[nt] = v0; o1[nt] = v1;
                ss += v0 * v0 + v1 * v1;
            }
            ss += __shfl_xor_sync(0xffffffffu, ss, 1);
            ss += __shfl_xor_sync(0xffffffffu, ss, 2);
            float sc = 1.0f / fmaxf(sqrtf(ss), 1e-12f);

            int row = base + wid * 16 + h * 8 + (lane >> 2);
            if (row < N_NODES) {
                #pragma unroll
                for (int nt = 0; nt < 16; nt++)
                    out2[row * 64 + nt * 4 + (lane & 3)] =
                        make_float2(o0[nt] * sc, o1[nt] * sc);
            }
        }
        __syncthreads();
    }
}

// ---------------------------------------------------------------------------
extern "C" void kernel_launch(void* const* d_in, const int* in_sizes, int n_in,
                              void* d_out, int out_size) {
    const float4*    x4   = (const float4*)d_in[0];
    const long long* ei   = (const long long*)d_in[1];
    const float4*    W4   = (const float4*)d_in[2];
    const float*     bias = (const float*)d_in[3];
    float4*          out4 = (float4*)d_out;

    cudaFuncSetAttribute(gemm_norm_kernel,
                         cudaFuncAttributeMaxDynamicSharedMemorySize, SM_TOT);

    const int EB = (N_EDGES + 255) / 256;   // 3125

    k_prep<<<(XCHUNKS + 255) / 256, 256>>>(ei, x4);
    k_hist<<<EB, 256>>>(ei);
    k_scan<<<SCAN_BLOCKS, 256>>>();
    k_binfill<<<EB, 256>>>(ei);
    k_aggregate<<<(N_NODES * 32 + 255) / 256, 256>>>();
    gemm_norm_kernel<<<GEMM_GRID, 256, SM_TOT>>>(x4, W4, bias, out4);
}

// round 11
// speedup vs baseline: 1.0707x; 1.0707x over previous
#include <cuda_runtime.h>
#include <cuda_bf16.h>
#include <cstdint>

#define N_NODES 50000
#define N_EDGES 800000
#define SCAN_BLOCKS ((N_NODES + 255) / 256)   // 196
#define GEMM_ROWS 128
#define NTILES ((N_NODES + GEMM_ROWS - 1) / GEMM_ROWS)   // 391
#define GEMM_GRID 148

// ---- scratch (device globals; no allocs) ----
__device__ __align__(16) float4 g_neigh4[N_NODES * 32];   // mean-aggregated neigh
__device__ int g_deg_i[N_NODES];
__device__ int g_cursor[N_NODES];
__device__ int g_src_bin[N_EDGES];
__device__ int g_scan_val[SCAN_BLOCKS];
__device__ volatile int g_scan_flag[SCAN_BLOCKS];
__device__ int g_ei_is64;

// ---- dtype-agnostic edge index reads (int32 low-word loads even for int64
//      buffers: values < 50000 so the little-endian low word is the value) ----
__device__ __forceinline__ int load_src(const long long* ei, int e) {
    const int* p = (const int*)ei;
    return g_ei_is64 ? __ldg(p + 2 * e) : __ldg(p + e);
}
__device__ __forceinline__ int load_dst(const long long* ei, int e) {
    const int* p = (const int*)ei;
    return g_ei_is64 ? __ldg(p + 2 * (N_EDGES + e)) : __ldg(p + N_EDGES + e);
}

// ===========================================================================
// K1: zero counters + probe edge_index dtype
// ===========================================================================
__global__ void __launch_bounds__(256) k_zero(const long long* __restrict__ ei) {
    int i = blockIdx.x * blockDim.x + threadIdx.x;
    if (i < N_NODES) g_deg_i[i] = 0;
    if (i < SCAN_BLOCKS) g_scan_flag[i] = 0;
    if (i == 0) {
        int ok = 1;
        for (int k = 0; k < 64; k++) {
            long long v = ei[k];
            if (v < 0 || v >= N_NODES) { ok = 0; break; }
        }
        g_ei_is64 = ok;
    }
}

// ===========================================================================
// K2: in-degree histogram
// ===========================================================================
__global__ void __launch_bounds__(256) k_hist(const long long* __restrict__ ei) {
    int e = blockIdx.x * blockDim.x + threadIdx.x;
    if (e >= N_EDGES) return;
    int d = load_dst(ei, e);
    if ((unsigned)d < N_NODES) atomicAdd(&g_deg_i[d], 1);
}

// ===========================================================================
// K3: single-pass exclusive scan (full lookback; flags re-zeroed by k_zero)
// ===========================================================================
__global__ void __launch_bounds__(256) k_scan() {
    __shared__ int s[256];
    __shared__ int carry;
    const int b = blockIdx.x;
    const int tid = threadIdx.x;
    const int i = b * 256 + tid;

    int v = (i < N_NODES) ? g_deg_i[i] : 0;
    s[tid] = v;
    __syncthreads();
    int acc = v;
    #pragma unroll
    for (int off = 1; off < 256; off <<= 1) {
        int t = (tid >= off) ? s[tid - off] : 0;
        __syncthreads();
        acc += t;
        s[tid] = acc;
        __syncthreads();
    }
    if (tid == 255) {
        g_scan_val[b] = acc;
        __threadfence();
        g_scan_flag[b] = 1;
    }
    if (tid == 0) carry = 0;
    __syncthreads();

    int sum = 0;
    for (int p = tid; p < b; p += 256) {
        while (g_scan_flag[p] == 0) { }
        sum += g_scan_val[p];
    }
    if (sum) atomicAdd(&carry, sum);
    __syncthreads();

    if (i < N_NODES) g_cursor[i] = carry + (acc - v);
}

// ===========================================================================
// K4: bin fill — counting-sort src ids by dst
// ===========================================================================
__global__ void __launch_bounds__(256) k_binfill(const long long* __restrict__ ei) {
    int e = blockIdx.x * blockDim.x + threadIdx.x;
    if (e >= N_EDGES) return;
    int s = load_src(ei, e);
    int d = load_dst(ei, e);
    if ((unsigned)s >= N_NODES || (unsigned)d >= N_NODES) return;
    int pos = atomicAdd(&g_cursor[d], 1);
    g_src_bin[pos] = s;
}

// ===========================================================================
// K5: gather-aggregate (fp32, reverted from bf16). One warp per node;
// lane = float4 chunk. 4-way edge unroll -> 4 independent 512B gathers in
// flight per warp (was 2) to cover L2 latency on low-degree nodes.
// ===========================================================================
__global__ void __launch_bounds__(256) k_aggregate(const float4* __restrict__ x4) {
    int n = (blockIdx.x * blockDim.x + threadIdx.x) >> 5;
    int lane = threadIdx.x & 31;
    if (n >= N_NODES) return;

    int end = g_cursor[n];
    int deg = g_deg_i[n];
    int beg = end - deg;

    float4 a0 = make_float4(0.f, 0.f, 0.f, 0.f);
    float4 a1 = make_float4(0.f, 0.f, 0.f, 0.f);
    float4 a2 = make_float4(0.f, 0.f, 0.f, 0.f);
    float4 a3 = make_float4(0.f, 0.f, 0.f, 0.f);

    for (int base = beg; base < end; base += 32) {
        int m = min(32, end - base);
        int s = (base + lane < end) ? __ldg(g_src_bin + base + lane) : 0;
        int j = 0;
        for (; j + 3 < m; j += 4) {
            int s0 = __shfl_sync(0xffffffffu, s, j);
            int s1 = __shfl_sync(0xffffffffu, s, j + 1);
            int s2 = __shfl_sync(0xffffffffu, s, j + 2);
            int s3 = __shfl_sync(0xffffffffu, s, j + 3);
            float4 v0 = __ldg(x4 + s0 * 32 + lane);
            float4 v1 = __ldg(x4 + s1 * 32 + lane);
            float4 v2 = __ldg(x4 + s2 * 32 + lane);
            float4 v3 = __ldg(x4 + s3 * 32 + lane);
            a0.x += v0.x; a0.y += v0.y; a0.z += v0.z; a0.w += v0.w;
            a1.x += v1.x; a1.y += v1.y; a1.z += v1.z; a1.w += v1.w;
            a2.x += v2.x; a2.y += v2.y; a2.z += v2.z; a2.w += v2.w;
            a3.x += v3.x; a3.y += v3.y; a3.z += v3.z; a3.w += v3.w;
        }
        for (; j < m; j++) {
            int s0 = __shfl_sync(0xffffffffu, s, j);
            float4 v0 = __ldg(x4 + s0 * 32 + lane);
            a0.x += v0.x; a0.y += v0.y; a0.z += v0.z; a0.w += v0.w;
        }
    }
    float sc = 1.0f / fmaxf((float)deg, 1.0f);
    g_neigh4[n * 32 + lane] =
        make_float4(((a0.x + a1.x) + (a2.x + a3.x)) * sc,
                    ((a0.y + a1.y) + (a2.y + a3.y)) * sc,
                    ((a0.z + a1.z) + (a2.z + a3.z)) * sc,
                    ((a0.w + a1.w) + (a2.w + a3.w)) * sc);
}

// ===========================================================================
// K6: mma.sync bf16-split GEMM + bias + row L2-normalize (persistent).
// (unchanged from R9 — passing at rel_err 4e-6)
// ===========================================================================
#define GSTRIDE 528
#define SM_BIAS 0
#define SM_A    1024
#define SM_BHI  (SM_A   + 128 * GSTRIDE)
#define SM_BLO  (SM_BHI + 128 * GSTRIDE)
#define SM_TOT  (SM_BLO + 128 * GSTRIDE)   // 203776 B

__device__ __forceinline__ uint32_t smem_u32(const void* p) {
    uint32_t a;
    asm("{ .reg .u64 t; cvta.to.shared.u64 t, %1; cvt.u32.u64 %0, t; }" : "=r"(a) : "l"(p));
    return a;
}

__device__ __forceinline__ void ldsm_x4(uint32_t& r0, uint32_t& r1, uint32_t& r2,
                                        uint32_t& r3, uint32_t addr) {
    asm volatile("ldmatrix.sync.aligned.m8n8.x4.shared.b16 {%0,%1,%2,%3}, [%4];"
                 : "=r"(r0), "=r"(r1), "=r"(r2), "=r"(r3) : "r"(addr));
}

__device__ __forceinline__ void mma_bf16(float* c, const uint32_t* a, const uint32_t* b) {
    asm volatile(
        "mma.sync.aligned.m16n8k16.row.col.f32.bf16.bf16.f32 "
        "{%0,%1,%2,%3}, {%4,%5,%6,%7}, {%8,%9}, {%0,%1,%2,%3};"
        : "+f"(c[0]), "+f"(c[1]), "+f"(c[2]), "+f"(c[3])
        : "r"(a[0]), "r"(a[1]), "r"(a[2]), "r"(a[3]), "r"(b[0]), "r"(b[1]));
}

__device__ __forceinline__ uint2 cvt_hi4(float4 v) {
    __nv_bfloat162 a = __floats2bfloat162_rn(v.x, v.y);
    __nv_bfloat162 b = __floats2bfloat162_rn(v.z, v.w);
    uint2 r;
    r.x = *reinterpret_cast<uint32_t*>(&a);
    r.y = *reinterpret_cast<uint32_t*>(&b);
    return r;
}
__device__ __forceinline__ uint2 cvt_lo4(float4 v) {
    __nv_bfloat162 a = __floats2bfloat162_rn(v.x, v.y);
    __nv_bfloat162 b = __floats2bfloat162_rn(v.z, v.w);
    float4 l = make_float4(v.x - __bfloat162float(a.x), v.y - __bfloat162float(a.y),
                           v.z - __bfloat162float(b.x), v.w - __bfloat162float(b.y));
    __nv_bfloat162 c = __floats2bfloat162_rn(l.x, l.y);
    __nv_bfloat162 d = __floats2bfloat162_rn(l.z, l.w);
    uint2 r;
    r.x = *reinterpret_cast<uint32_t*>(&c);
    r.y = *reinterpret_cast<uint32_t*>(&d);
    return r;
}

// one bf16 pass: C += A_warp_tile(16xK) @ B_tile(128xK)^T  -> 16x128
__device__ __forceinline__ void run_pass(uint32_t aA, const uint32_t* bA,
                                         float (*c)[4]) {
    #pragma unroll 4
    for (int k = 0; k < 16; k++) {
        uint32_t a[4], b[16][2];
        ldsm_x4(a[0], a[1], a[2], a[3], aA + k * 32);
        #pragma unroll
        for (int p = 0; p < 8; p++)
            ldsm_x4(b[2*p][0], b[2*p][1], b[2*p+1][0], b[2*p+1][1], bA[p] + k * 32);
        #pragma unroll
        for (int nt = 0; nt < 16; nt++)
            mma_bf16(c[nt], a, b[nt]);
    }
}

__global__ void __launch_bounds__(256, 1) gemm_norm_kernel(
    const float4* __restrict__ x4,
    const float4* __restrict__ W4,     // [128][64] float4 (W[c][k])
    const float*  __restrict__ bias,   // [128]
    float4*       __restrict__ out4)   // [N_NODES][32]
{
    extern __shared__ char smem[];
    const uint32_t sb = smem_u32(smem);
    const int tid  = threadIdx.x;
    const int lane = tid & 31;
    const int wid  = tid >> 5;      // warp w -> rows w*16..+15, all 128 cols

    for (int i = tid; i < 8192; i += 256) {
        int c = i >> 6, k4 = i & 63;
        float4 v = __ldg(W4 + i);
        uint32_t off = (uint32_t)(c * GSTRIDE + k4 * 8);
        *reinterpret_cast<uint2*>(smem + SM_BHI + off) = cvt_hi4(v);
        *reinterpret_cast<uint2*>(smem + SM_BLO + off) = cvt_lo4(v);
    }
    if (tid < 128) ((float*)(smem + SM_BIAS))[tid] = __ldg(bias + tid);
    __syncthreads();

    const int q = lane >> 3, r = lane & 7;
    const uint32_t aRel = (uint32_t)((wid * 16 + (q & 1) * 8 + r) * GSTRIDE + (q >> 1) * 16);
    uint32_t bRel[8];
    #pragma unroll
    for (int p = 0; p < 8; p++)
        bRel[p] = (uint32_t)((p * 16 + (q >> 1) * 8 + r) * GSTRIDE + (q & 1) * 16);

    float2* out2 = (float2*)out4;
    const float* bs = (const float*)(smem + SM_BIAS);

    for (int tile = blockIdx.x; tile < NTILES; tile += GEMM_GRID) {
        const int base = tile * GEMM_ROWS;

        for (int i = tid; i < 8192; i += 256) {
            int rr = i >> 6, k4 = i & 63;
            int row = base + rr;
            float4 v = make_float4(0.f, 0.f, 0.f, 0.f);
            if (row < N_NODES)
                v = (k4 < 32) ? __ldg(x4 + row * 32 + k4)
                              : g_neigh4[row * 32 + (k4 - 32)];
            *reinterpret_cast<uint2*>(smem + SM_A + rr * GSTRIDE + k4 * 8) = cvt_hi4(v);
        }
        __syncthreads();

        float c[16][4];
        #pragma unroll
        for (int nt = 0; nt < 16; nt++)
            #pragma unroll
            for (int j = 0; j < 4; j++) c[nt][j] = 0.f;

        uint32_t bHi[8], bLo[8];
        #pragma unroll
        for (int p = 0; p < 8; p++) {
            bHi[p] = sb + SM_BHI + bRel[p];
            bLo[p] = sb + SM_BLO + bRel[p];
        }

        run_pass(sb + SM_A + aRel, bHi, c);
        run_pass(sb + SM_A + aRel, bLo, c);
        __syncthreads();

        for (int i = tid; i < 8192; i += 256) {
            int rr = i >> 6, k4 = i & 63;
            int row = base + rr;
            float4 v = make_float4(0.f, 0.f, 0.f, 0.f);
            if (row < N_NODES)
                v = (k4 < 32) ? __ldg(x4 + row * 32 + k4)
                              : g_neigh4[row * 32 + (k4 - 32)];
            *reinterpret_cast<uint2*>(smem + SM_A + rr * GSTRIDE + k4 * 8) = cvt_lo4(v);
        }
        __syncthreads();

        run_pass(sb + SM_A + aRel, bHi, c);

        #pragma unroll
        for (int h = 0; h < 2; h++) {
            float o0[16], o1[16];
            float ss = 0.f;
            #pragma unroll
            for (int nt = 0; nt < 16; nt++) {
                int col = nt * 8 + (lane & 3) * 2;
                float v0 = c[nt][2*h + 0] + bs[col + 0];
                float v1 = c[nt][2*h + 1] + bs[col + 1];
                o0[nt] = v0; o1[nt] = v1;
                ss += v0 * v0 + v1 * v1;
            }
            ss += __shfl_xor_sync(0xffffffffu, ss, 1);
            ss += __shfl_xor_sync(0xffffffffu, ss, 2);
            float sc = 1.0f / fmaxf(sqrtf(ss), 1e-12f);

            int row = base + wid * 16 + h * 8 + (lane >> 2);
            if (row < N_NODES) {
                #pragma unroll
                for (int nt = 0; nt < 16; nt++)
                    out2[row * 64 + nt * 4 + (lane & 3)] =
                        make_float2(o0[nt] * sc, o1[nt] * sc);
            }
        }
        __syncthreads();
    }
}

// ---------------------------------------------------------------------------
extern "C" void kernel_launch(void* const* d_in, const int* in_sizes, int n_in,
                              void* d_out, int out_size) {
    const float4*    x4   = (const float4*)d_in[0];
    const long long* ei   = (const long long*)d_in[1];
    const float4*    W4   = (const float4*)d_in[2];
    const float*     bias = (const float*)d_in[3];
    float4*          out4 = (float4*)d_out;

    cudaFuncSetAttribute(gemm_norm_kernel,
                         cudaFuncAttributeMaxDynamicSharedMemorySize, SM_TOT);

    const int EB = (N_EDGES + 255) / 256;   // 3125

    k_zero<<<SCAN_BLOCKS, 256>>>(ei);
    k_hist<<<EB, 256>>>(ei);
    k_scan<<<SCAN_BLOCKS, 256>>>();
    k_binfill<<<EB, 256>>>(ei);
    k_aggregate<<<(N_NODES * 32 + 255) / 256, 256>>>(x4);
    gemm_norm_kernel<<<GEMM_GRID, 256, SM_TOT>>>(x4, W4, bias, out4);
}

// round 12
// speedup vs baseline: 1.0829x; 1.0114x over previous
#include <cuda_runtime.h>
#include <cuda_bf16.h>
#include <cstdint>

#define N_NODES 50000
#define N_EDGES 800000
#define SCAN_BLOCKS ((N_NODES + 255) / 256)   // 196 virtual scan tiles
#define COOP_GRID 296                          // 2 blocks/SM, all resident
#define GSZ (COOP_GRID * 256)
#define AGG_WARPS (COOP_GRID * 8)
#define GEMM_ROWS 64
#define NTILES ((N_NODES + GEMM_ROWS - 1) / GEMM_ROWS)   // 782
#define GEMM_GRID 148

// ---- scratch (device globals; no allocs) ----
__device__ __align__(16) float4 g_neigh4[N_NODES * 32];
__device__ int g_deg_i[N_NODES];
__device__ int g_cursor[N_NODES];
__device__ int g_src_bin[N_EDGES];
__device__ int g_scan_val[SCAN_BLOCKS];
__device__ int g_ei_is64;
__device__ int g_bar_count;          // self-resets each barrier -> replay-safe
__device__ volatile int g_bar_gen;   // monotonically increasing; relative compare

// ---- dtype-agnostic edge index reads (int32 low-word: values < 50000) ----
__device__ __forceinline__ int load_src(const long long* ei, int e) {
    const int* p = (const int*)ei;
    return g_ei_is64 ? __ldg(p + 2 * e) : __ldg(p + e);
}
__device__ __forceinline__ int load_dst(const long long* ei, int e) {
    const int* p = (const int*)ei;
    return g_ei_is64 ? __ldg(p + 2 * (N_EDGES + e)) : __ldg(p + N_EDGES + e);
}

// ---- grid-wide barrier (all COOP_GRID blocks resident) ----
__device__ __forceinline__ void grid_bar() {
    __threadfence();
    __syncthreads();
    if (threadIdx.x == 0) {
        int my = g_bar_gen;
        if (atomicAdd(&g_bar_count, 1) == COOP_GRID - 1) {
            g_bar_count = 0;
            __threadfence();
            g_bar_gen = my + 1;
        } else {
            while (g_bar_gen == my) { }
            __threadfence();
        }
    }
    __syncthreads();
}

// ===========================================================================
// K1: ONE persistent kernel: zero+probe | hist | scan | binfill | aggregate
// ===========================================================================
__global__ void __launch_bounds__(256, 2) k_edges(const long long* __restrict__ ei,
                                                  const float4* __restrict__ x4) {
    __shared__ int s[256];
    __shared__ int wsum[8];
    const int tid  = threadIdx.x;
    const int gtid = blockIdx.x * 256 + tid;
    const int lane = tid & 31;

    // ---- phase 0: zero counters + dtype probe ----
    for (int i = gtid; i < N_NODES; i += GSZ) g_deg_i[i] = 0;
    if (gtid == 0) {
        int ok = 1;
        for (int k = 0; k < 64; k++) {
            long long v = ei[k];
            if (v < 0 || v >= N_NODES) { ok = 0; break; }
        }
        g_ei_is64 = ok;
    }
    grid_bar();

    // ---- phase 1: in-degree histogram ----
    for (int e = gtid; e < N_EDGES; e += GSZ) {
        int d = load_dst(ei, e);
        if ((unsigned)d < N_NODES) atomicAdd(&g_deg_i[d], 1);
    }
    grid_bar();

    // ---- phase 2a: per-virtual-tile sums (196 tiles of 256) ----
    for (int vt = blockIdx.x; vt < SCAN_BLOCKS; vt += COOP_GRID) {
        int i = vt * 256 + tid;
        int v = (i < N_NODES) ? g_deg_i[i] : 0;
        #pragma unroll
        for (int o = 16; o; o >>= 1) v += __shfl_xor_sync(0xffffffffu, v, o);
        if (lane == 0) wsum[tid >> 5] = v;
        __syncthreads();
        if (tid == 0) {
            int t = 0;
            #pragma unroll
            for (int j = 0; j < 8; j++) t += wsum[j];
            g_scan_val[vt] = t;
        }
        __syncthreads();
    }
    grid_bar();

    // ---- phase 2b: block 0 exclusive-scans the 196 tile sums ----
    if (blockIdx.x == 0) {
        int v = (tid < SCAN_BLOCKS) ? g_scan_val[tid] : 0;
        s[tid] = v;
        __syncthreads();
        int acc = v;
        #pragma unroll
        for (int off = 1; off < 256; off <<= 1) {
            int t = (tid >= off) ? s[tid - off] : 0;
            __syncthreads();
            acc += t;
            s[tid] = acc;
            __syncthreads();
        }
        if (tid < SCAN_BLOCKS) g_scan_val[tid] = acc - v;
    }
    grid_bar();

    // ---- phase 2c: per-tile exclusive scan + base -> cursor ----
    for (int vt = blockIdx.x; vt < SCAN_BLOCKS; vt += COOP_GRID) {
        int i = vt * 256 + tid;
        int v = (i < N_NODES) ? g_deg_i[i] : 0;
        s[tid] = v;
        __syncthreads();
        int acc = v;
        #pragma unroll
        for (int off = 1; off < 256; off <<= 1) {
            int t = (tid >= off) ? s[tid - off] : 0;
            __syncthreads();
            acc += t;
            s[tid] = acc;
            __syncthreads();
        }
        if (i < N_NODES) g_cursor[i] = g_scan_val[vt] + acc - v;
        __syncthreads();
    }
    grid_bar();

    // ---- phase 3: bin fill (counting-sort src by dst) ----
    for (int e = gtid; e < N_EDGES; e += GSZ) {
        int sr = load_src(ei, e);
        int d  = load_dst(ei, e);
        if ((unsigned)sr >= N_NODES || (unsigned)d >= N_NODES) continue;
        int pos = atomicAdd(&g_cursor[d], 1);
        g_src_bin[pos] = sr;
    }
    grid_bar();

    // ---- phase 4: gather-aggregate (warp/node, 4-way MLP unroll) ----
    for (int n = gtid >> 5; n < N_NODES; n += AGG_WARPS) {
        int end = g_cursor[n];
        int deg = g_deg_i[n];
        int beg = end - deg;

        float4 a0 = make_float4(0.f, 0.f, 0.f, 0.f);
        float4 a1 = make_float4(0.f, 0.f, 0.f, 0.f);
        float4 a2 = make_float4(0.f, 0.f, 0.f, 0.f);
        float4 a3 = make_float4(0.f, 0.f, 0.f, 0.f);

        for (int base = beg; base < end; base += 32) {
            int m = min(32, end - base);
            int sv = (base + lane < end) ? __ldg(g_src_bin + base + lane) : 0;
            int j = 0;
            for (; j + 3 < m; j += 4) {
                int s0 = __shfl_sync(0xffffffffu, sv, j);
                int s1 = __shfl_sync(0xffffffffu, sv, j + 1);
                int s2 = __shfl_sync(0xffffffffu, sv, j + 2);
                int s3 = __shfl_sync(0xffffffffu, sv, j + 3);
                float4 v0 = __ldg(x4 + s0 * 32 + lane);
                float4 v1 = __ldg(x4 + s1 * 32 + lane);
                float4 v2 = __ldg(x4 + s2 * 32 + lane);
                float4 v3 = __ldg(x4 + s3 * 32 + lane);
                a0.x += v0.x; a0.y += v0.y; a0.z += v0.z; a0.w += v0.w;
                a1.x += v1.x; a1.y += v1.y; a1.z += v1.z; a1.w += v1.w;
                a2.x += v2.x; a2.y += v2.y; a2.z += v2.z; a2.w += v2.w;
                a3.x += v3.x; a3.y += v3.y; a3.z += v3.z; a3.w += v3.w;
            }
            for (; j < m; j++) {
                int s0 = __shfl_sync(0xffffffffu, sv, j);
                float4 v0 = __ldg(x4 + s0 * 32 + lane);
                a0.x += v0.x; a0.y += v0.y; a0.z += v0.z; a0.w += v0.w;
            }
        }
        float sc = 1.0f / fmaxf((float)deg, 1.0f);
        g_neigh4[n * 32 + lane] =
            make_float4(((a0.x + a1.x) + (a2.x + a3.x)) * sc,
                        ((a0.y + a1.y) + (a2.y + a3.y)) * sc,
                        ((a0.z + a1.z) + (a2.z + a3.z)) * sc,
                        ((a0.w + a1.w) + (a2.w + a3.w)) * sc);
    }
}

// ===========================================================================
// K2: mma.sync bf16-split GEMM + bias + row L2-normalize (persistent).
// 64-row tiles; A_hi AND A_lo staged once; single k-loop interleaves the
// 3 passes (per k: 10 LDSM -> 24 HMMA). 8 warps = 4 m-groups x 2 n-halves;
// row norm combined across the 2 halves via smem.
// ===========================================================================
#define GSTRIDE 528
#define SM_BIAS  0                               // 128 floats
#define SM_NORM  512                             // 64 rows x 2 floats
#define SM_AHI   1024
#define SM_ALO   (SM_AHI + 64 * GSTRIDE)         // +33792
#define SM_BHI   (SM_ALO + 64 * GSTRIDE)
#define SM_BLO   (SM_BHI + 128 * GSTRIDE)
#define SM_TOT   (SM_BLO + 128 * GSTRIDE)        // 203776 B

__device__ __forceinline__ uint32_t smem_u32(const void* p) {
    uint32_t a;
    asm("{ .reg .u64 t; cvta.to.shared.u64 t, %1; cvt.u32.u64 %0, t; }" : "=r"(a) : "l"(p));
    return a;
}
__device__ __forceinline__ void ldsm_x4(uint32_t& r0, uint32_t& r1, uint32_t& r2,
                                        uint32_t& r3, uint32_t addr) {
    asm volatile("ldmatrix.sync.aligned.m8n8.x4.shared.b16 {%0,%1,%2,%3}, [%4];"
                 : "=r"(r0), "=r"(r1), "=r"(r2), "=r"(r3) : "r"(addr));
}
__device__ __forceinline__ void mma_bf16(float* c, const uint32_t* a, const uint32_t* b) {
    asm volatile(
        "mma.sync.aligned.m16n8k16.row.col.f32.bf16.bf16.f32 "
        "{%0,%1,%2,%3}, {%4,%5,%6,%7}, {%8,%9}, {%0,%1,%2,%3};"
        : "+f"(c[0]), "+f"(c[1]), "+f"(c[2]), "+f"(c[3])
        : "r"(a[0]), "r"(a[1]), "r"(a[2]), "r"(a[3]), "r"(b[0]), "r"(b[1]));
}
__device__ __forceinline__ uint2 cvt_hi4(float4 v) {
    __nv_bfloat162 a = __floats2bfloat162_rn(v.x, v.y);
    __nv_bfloat162 b = __floats2bfloat162_rn(v.z, v.w);
    uint2 r;
    r.x = *reinterpret_cast<uint32_t*>(&a);
    r.y = *reinterpret_cast<uint32_t*>(&b);
    return r;
}
__device__ __forceinline__ uint2 cvt_lo4(float4 v) {
    __nv_bfloat162 a = __floats2bfloat162_rn(v.x, v.y);
    __nv_bfloat162 b = __floats2bfloat162_rn(v.z, v.w);
    float4 l = make_float4(v.x - __bfloat162float(a.x), v.y - __bfloat162float(a.y),
                           v.z - __bfloat162float(b.x), v.w - __bfloat162float(b.y));
    __nv_bfloat162 c = __floats2bfloat162_rn(l.x, l.y);
    __nv_bfloat162 d = __floats2bfloat162_rn(l.z, l.w);
    uint2 r;
    r.x = *reinterpret_cast<uint32_t*>(&c);
    r.y = *reinterpret_cast<uint32_t*>(&d);
    return r;
}

__global__ void __launch_bounds__(256, 1) gemm_norm_kernel(
    const float4* __restrict__ x4,
    const float4* __restrict__ W4,     // [128][64] float4 (W[c][k])
    const float*  __restrict__ bias,   // [128]
    float4*       __restrict__ out4)   // [N_NODES][32]
{
    extern __shared__ char smem[];
    const uint32_t sb = smem_u32(smem);
    const int tid  = threadIdx.x;
    const int lane = tid & 31;
    const int wid  = tid >> 5;
    const int g    = wid >> 1;     // m-group: rows g*16..+15
    const int h    = wid & 1;      // n-half:  cols h*64..+63

    // Stage W -> B_hi/B_lo (once) + bias
    for (int i = tid; i < 8192; i += 256) {
        int c = i >> 6, k4 = i & 63;
        float4 v = __ldg(W4 + i);
        uint32_t off = (uint32_t)(c * GSTRIDE + k4 * 8);
        *reinterpret_cast<uint2*>(smem + SM_BHI + off) = cvt_hi4(v);
        *reinterpret_cast<uint2*>(smem + SM_BLO + off) = cvt_lo4(v);
    }
    if (tid < 128) ((float*)(smem + SM_BIAS))[tid] = __ldg(bias + tid);
    __syncthreads();

    const int q = lane >> 3, r = lane & 7;
    const uint32_t aRel = (uint32_t)((g * 16 + (q & 1) * 8 + r) * GSTRIDE + (q >> 1) * 16);
    const uint32_t aHiA = sb + SM_AHI + aRel;
    const uint32_t aLoA = sb + SM_ALO + aRel;
    uint32_t bHiA[4], bLoA[4];
    #pragma unroll
    for (int p = 0; p < 4; p++) {
        uint32_t bRel = (uint32_t)((h * 64 + p * 16 + (q >> 1) * 8 + r) * GSTRIDE + (q & 1) * 16);
        bHiA[p] = sb + SM_BHI + bRel;
        bLoA[p] = sb + SM_BLO + bRel;
    }

    float2* out2 = (float2*)out4;
    const float* bs = (const float*)(smem + SM_BIAS);
    float* snorm = (float*)(smem + SM_NORM);

    for (int tile = blockIdx.x; tile < NTILES; tile += GEMM_GRID) {
        const int base = tile * GEMM_ROWS;

        // ---- stage A_hi AND A_lo (single fp32 read) ----
        for (int i = tid; i < 4096; i += 256) {
            int rr = i >> 6, k4 = i & 63;
            int row = base + rr;
            float4 v = make_float4(0.f, 0.f, 0.f, 0.f);
            if (row < N_NODES)
                v = (k4 < 32) ? __ldg(x4 + row * 32 + k4)
                              : g_neigh4[row * 32 + (k4 - 32)];
            uint32_t off = (uint32_t)(rr * GSTRIDE + k4 * 8);
            *reinterpret_cast<uint2*>(smem + SM_AHI + off) = cvt_hi4(v);
            *reinterpret_cast<uint2*>(smem + SM_ALO + off) = cvt_lo4(v);
        }
        __syncthreads();

        float c[8][4];
        #pragma unroll
        for (int nt = 0; nt < 8; nt++)
            #pragma unroll
            for (int j = 0; j < 4; j++) c[nt][j] = 0.f;

        // ---- single k-loop, 3 interleaved bf16 passes ----
        #pragma unroll 4
        for (int k = 0; k < 16; k++) {
            uint32_t ah[4], al[4], bh[8][2], bl[8][2];
            ldsm_x4(ah[0], ah[1], ah[2], ah[3], aHiA + k * 32);
            ldsm_x4(al[0], al[1], al[2], al[3], aLoA + k * 32);
            #pragma unroll
            for (int p = 0; p < 4; p++) {
                ldsm_x4(bh[2*p][0], bh[2*p][1], bh[2*p+1][0], bh[2*p+1][1], bHiA[p] + k * 32);
                ldsm_x4(bl[2*p][0], bl[2*p][1], bl[2*p+1][0], bl[2*p+1][1], bLoA[p] + k * 32);
            }
            #pragma unroll
            for (int nt = 0; nt < 8; nt++) {
                mma_bf16(c[nt], ah, bh[nt]);
                mma_bf16(c[nt], ah, bl[nt]);
                mma_bf16(c[nt], al, bh[nt]);
            }
        }

        // ---- epilogue 1: per-half partial row norms -> smem ----
        #pragma unroll
        for (int h2 = 0; h2 < 2; h2++) {
            float ss = 0.f;
            #pragma unroll
            for (int nt = 0; nt < 8; nt++) {
                int col = h * 64 + nt * 8 + (lane & 3) * 2;
                float v0 = c[nt][2*h2 + 0] + bs[col + 0];
                float v1 = c[nt][2*h2 + 1] + bs[col + 1];
                ss += v0 * v0 + v1 * v1;
            }
            ss += __shfl_xor_sync(0xffffffffu, ss, 1);
            ss += __shfl_xor_sync(0xffffffffu, ss, 2);
            if ((lane & 3) == 0)
                snorm[(g * 16 + h2 * 8 + (lane >> 2)) * 2 + h] = ss;
        }
        __syncthreads();

        // ---- epilogue 2: combine halves, normalize, store ----
        #pragma unroll
        for (int h2 = 0; h2 < 2; h2++) {
            int rl = g * 16 + h2 * 8 + (lane >> 2);
            float ss = snorm[rl * 2] + snorm[rl * 2 + 1];
            float sc = 1.0f / fmaxf(sqrtf(ss), 1e-12f);
            int row = base + rl;
            if (row < N_NODES) {
                #pragma unroll
                for (int nt = 0; nt < 8; nt++) {
                    int col = h * 64 + nt * 8 + (lane & 3) * 2;
                    float v0 = c[nt][2*h2 + 0] + bs[col + 0];
                    float v1 = c[nt][2*h2 + 1] + bs[col + 1];
                    out2[row * 64 + h * 32 + nt * 4 + (lane & 3)] =
                        make_float2(v0 * sc, v1 * sc);
                }
            }
        }
        __syncthreads();   // snorm/A reused next tile
    }
}

// ---------------------------------------------------------------------------
extern "C" void kernel_launch(void* const* d_in, const int* in_sizes, int n_in,
                              void* d_out, int out_size) {
    const float4*    x4   = (const float4*)d_in[0];
    const long long* ei   = (const long long*)d_in[1];
    const float4*    W4   = (const float4*)d_in[2];
    const float*     bias = (const float*)d_in[3];
    float4*          out4 = (float4*)d_out;

    cudaFuncSetAttribute(gemm_norm_kernel,
                         cudaFuncAttributeMaxDynamicSharedMemorySize, SM_TOT);

    k_edges<<<COOP_GRID, 256>>>(ei, x4);
    gemm_norm_kernel<<<GEMM_GRID, 256, SM_TOT>>>(x4, W4, bias, out4);
}

// round 13
// speedup vs baseline: 1.1606x; 1.0717x over previous
#include <cuda_runtime.h>
#include <cuda_bf16.h>
#include <cstdint>

#define N_NODES 50000
#define N_EDGES 800000
#define SCAN_BLOCKS ((N_NODES + 255) / 256)   // 196 virtual scan tiles
#define COOP_GRID 296                          // 2 blocks/SM, all resident
#define GSZ (COOP_GRID * 256)
#define AGG_WARPS (COOP_GRID * 8)
#define GEMM_ROWS 64
#define NTILES ((N_NODES + GEMM_ROWS - 1) / GEMM_ROWS)   // 782
#define GEMM_GRID 148
#define GEMM_THREADS 512

// ---- scratch (device globals; no allocs) ----
__device__ __align__(16) float4 g_neigh4[N_NODES * 32];
__device__ int g_deg_i[N_NODES];
__device__ int g_cursor[N_NODES];
__device__ int g_src_bin[N_EDGES];
__device__ int g_scan_val[SCAN_BLOCKS];
__device__ int g_ei_is64;
__device__ int g_bar_count;          // self-resets each barrier -> replay-safe
__device__ volatile int g_bar_gen;   // monotonically increasing; relative compare

// ---- dtype-agnostic edge index reads (int32 low-word: values < 50000) ----
__device__ __forceinline__ int load_src(const long long* ei, int e) {
    const int* p = (const int*)ei;
    return g_ei_is64 ? __ldg(p + 2 * e) : __ldg(p + e);
}
__device__ __forceinline__ int load_dst(const long long* ei, int e) {
    const int* p = (const int*)ei;
    return g_ei_is64 ? __ldg(p + 2 * (N_EDGES + e)) : __ldg(p + N_EDGES + e);
}

// ---- grid-wide barrier (all COOP_GRID blocks resident) ----
__device__ __forceinline__ void grid_bar() {
    __threadfence();
    __syncthreads();
    if (threadIdx.x == 0) {
        int my = g_bar_gen;
        if (atomicAdd(&g_bar_count, 1) == COOP_GRID - 1) {
            g_bar_count = 0;
            __threadfence();
            g_bar_gen = my + 1;
        } else {
            while (g_bar_gen == my) { }
            __threadfence();
        }
    }
    __syncthreads();
}

// ===========================================================================
// K1: ONE persistent kernel: zero+probe | hist | scan | binfill | aggregate
// (unchanged from R12 — measured good: ~58 us for the whole edge pipeline)
// ===========================================================================
__global__ void __launch_bounds__(256, 2) k_edges(const long long* __restrict__ ei,
                                                  const float4* __restrict__ x4) {
    __shared__ int s[256];
    __shared__ int wsum[8];
    const int tid  = threadIdx.x;
    const int gtid = blockIdx.x * 256 + tid;
    const int lane = tid & 31;

    // ---- phase 0: zero counters + dtype probe ----
    for (int i = gtid; i < N_NODES; i += GSZ) g_deg_i[i] = 0;
    if (gtid == 0) {
        int ok = 1;
        for (int k = 0; k < 64; k++) {
            long long v = ei[k];
            if (v < 0 || v >= N_NODES) { ok = 0; break; }
        }
        g_ei_is64 = ok;
    }
    grid_bar();

    // ---- phase 1: in-degree histogram ----
    for (int e = gtid; e < N_EDGES; e += GSZ) {
        int d = load_dst(ei, e);
        if ((unsigned)d < N_NODES) atomicAdd(&g_deg_i[d], 1);
    }
    grid_bar();

    // ---- phase 2a: per-virtual-tile sums ----
    for (int vt = blockIdx.x; vt < SCAN_BLOCKS; vt += COOP_GRID) {
        int i = vt * 256 + tid;
        int v = (i < N_NODES) ? g_deg_i[i] : 0;
        #pragma unroll
        for (int o = 16; o; o >>= 1) v += __shfl_xor_sync(0xffffffffu, v, o);
        if (lane == 0) wsum[tid >> 5] = v;
        __syncthreads();
        if (tid == 0) {
            int t = 0;
            #pragma unroll
            for (int j = 0; j < 8; j++) t += wsum[j];
            g_scan_val[vt] = t;
        }
        __syncthreads();
    }
    grid_bar();

    // ---- phase 2b: block 0 exclusive-scans the 196 tile sums ----
    if (blockIdx.x == 0) {
        int v = (tid < SCAN_BLOCKS) ? g_scan_val[tid] : 0;
        s[tid] = v;
        __syncthreads();
        int acc = v;
        #pragma unroll
        for (int off = 1; off < 256; off <<= 1) {
            int t = (tid >= off) ? s[tid - off] : 0;
            __syncthreads();
            acc += t;
            s[tid] = acc;
            __syncthreads();
        }
        if (tid < SCAN_BLOCKS) g_scan_val[tid] = acc - v;
    }
    grid_bar();

    // ---- phase 2c: per-tile exclusive scan + base -> cursor ----
    for (int vt = blockIdx.x; vt < SCAN_BLOCKS; vt += COOP_GRID) {
        int i = vt * 256 + tid;
        int v = (i < N_NODES) ? g_deg_i[i] : 0;
        s[tid] = v;
        __syncthreads();
        int acc = v;
        #pragma unroll
        for (int off = 1; off < 256; off <<= 1) {
            int t = (tid >= off) ? s[tid - off] : 0;
            __syncthreads();
            acc += t;
            s[tid] = acc;
            __syncthreads();
        }
        if (i < N_NODES) g_cursor[i] = g_scan_val[vt] + acc - v;
        __syncthreads();
    }
    grid_bar();

    // ---- phase 3: bin fill ----
    for (int e = gtid; e < N_EDGES; e += GSZ) {
        int sr = load_src(ei, e);
        int d  = load_dst(ei, e);
        if ((unsigned)sr >= N_NODES || (unsigned)d >= N_NODES) continue;
        int pos = atomicAdd(&g_cursor[d], 1);
        g_src_bin[pos] = sr;
    }
    grid_bar();

    // ---- phase 4: gather-aggregate (warp/node, 4-way MLP unroll) ----
    for (int n = gtid >> 5; n < N_NODES; n += AGG_WARPS) {
        int end = g_cursor[n];
        int deg = g_deg_i[n];
        int beg = end - deg;

        float4 a0 = make_float4(0.f, 0.f, 0.f, 0.f);
        float4 a1 = make_float4(0.f, 0.f, 0.f, 0.f);
        float4 a2 = make_float4(0.f, 0.f, 0.f, 0.f);
        float4 a3 = make_float4(0.f, 0.f, 0.f, 0.f);

        for (int base = beg; base < end; base += 32) {
            int m = min(32, end - base);
            int sv = (base + lane < end) ? __ldg(g_src_bin + base + lane) : 0;
            int j = 0;
            for (; j + 3 < m; j += 4) {
                int s0 = __shfl_sync(0xffffffffu, sv, j);
                int s1 = __shfl_sync(0xffffffffu, sv, j + 1);
                int s2 = __shfl_sync(0xffffffffu, sv, j + 2);
                int s3 = __shfl_sync(0xffffffffu, sv, j + 3);
                float4 v0 = __ldg(x4 + s0 * 32 + lane);
                float4 v1 = __ldg(x4 + s1 * 32 + lane);
                float4 v2 = __ldg(x4 + s2 * 32 + lane);
                float4 v3 = __ldg(x4 + s3 * 32 + lane);
                a0.x += v0.x; a0.y += v0.y; a0.z += v0.z; a0.w += v0.w;
                a1.x += v1.x; a1.y += v1.y; a1.z += v1.z; a1.w += v1.w;
                a2.x += v2.x; a2.y += v2.y; a2.z += v2.z; a2.w += v2.w;
                a3.x += v3.x; a3.y += v3.y; a3.z += v3.z; a3.w += v3.w;
            }
            for (; j < m; j++) {
                int s0 = __shfl_sync(0xffffffffu, sv, j);
                float4 v0 = __ldg(x4 + s0 * 32 + lane);
                a0.x += v0.x; a0.y += v0.y; a0.z += v0.z; a0.w += v0.w;
            }
        }
        float sc = 1.0f / fmaxf((float)deg, 1.0f);
        g_neigh4[n * 32 + lane] =
            make_float4(((a0.x + a1.x) + (a2.x + a3.x)) * sc,
                        ((a0.y + a1.y) + (a2.y + a3.y)) * sc,
                        ((a0.z + a1.z) + (a2.z + a3.z)) * sc,
                        ((a0.w + a1.w) + (a2.w + a3.w)) * sc);
    }
}

// ===========================================================================
// K2: mma.sync bf16-split GEMM, 512 THREADS (16 warps/SM — was 8; measured
// occ=12.5%, tensor=18%, issue=12% -> latency-bound, double the warps).
// 64-row tiles; A_hi+A_lo staged once; interleaved 3-pass k-loop.
// 16 warps = 4 m-groups x 4 n-quarters; warp tile 16x32; per k: 6 LDSM.x4
// -> 12 HMMA; c[4][4]=16 regs. Row norm combined across 4 quarters in smem.
// ===========================================================================
#define GSTRIDE 528
#define SM_BIAS  0                               // 128 floats
#define SM_NORM  512                             // 64 rows x 4 floats
#define SM_AHI   1536
#define SM_ALO   (SM_AHI + 64 * GSTRIDE)
#define SM_BHI   (SM_ALO + 64 * GSTRIDE)
#define SM_BLO   (SM_BHI + 128 * GSTRIDE)
#define SM_TOT   (SM_BLO + 128 * GSTRIDE)        // 204288 B

__device__ __forceinline__ uint32_t smem_u32(const void* p) {
    uint32_t a;
    asm("{ .reg .u64 t; cvta.to.shared.u64 t, %1; cvt.u32.u64 %0, t; }" : "=r"(a) : "l"(p));
    return a;
}
__device__ __forceinline__ void ldsm_x4(uint32_t& r0, uint32_t& r1, uint32_t& r2,
                                        uint32_t& r3, uint32_t addr) {
    asm volatile("ldmatrix.sync.aligned.m8n8.x4.shared.b16 {%0,%1,%2,%3}, [%4];"
                 : "=r"(r0), "=r"(r1), "=r"(r2), "=r"(r3) : "r"(addr));
}
__device__ __forceinline__ void mma_bf16(float* c, const uint32_t* a, const uint32_t* b) {
    asm volatile(
        "mma.sync.aligned.m16n8k16.row.col.f32.bf16.bf16.f32 "
        "{%0,%1,%2,%3}, {%4,%5,%6,%7}, {%8,%9}, {%0,%1,%2,%3};"
        : "+f"(c[0]), "+f"(c[1]), "+f"(c[2]), "+f"(c[3])
        : "r"(a[0]), "r"(a[1]), "r"(a[2]), "r"(a[3]), "r"(b[0]), "r"(b[1]));
}
__device__ __forceinline__ uint2 cvt_hi4(float4 v) {
    __nv_bfloat162 a = __floats2bfloat162_rn(v.x, v.y);
    __nv_bfloat162 b = __floats2bfloat162_rn(v.z, v.w);
    uint2 r;
    r.x = *reinterpret_cast<uint32_t*>(&a);
    r.y = *reinterpret_cast<uint32_t*>(&b);
    return r;
}
__device__ __forceinline__ uint2 cvt_lo4(float4 v) {
    __nv_bfloat162 a = __floats2bfloat162_rn(v.x, v.y);
    __nv_bfloat162 b = __floats2bfloat162_rn(v.z, v.w);
    float4 l = make_float4(v.x - __bfloat162float(a.x), v.y - __bfloat162float(a.y),
                           v.z - __bfloat162float(b.x), v.w - __bfloat162float(b.y));
    __nv_bfloat162 c = __floats2bfloat162_rn(l.x, l.y);
    __nv_bfloat162 d = __floats2bfloat162_rn(l.z, l.w);
    uint2 r;
    r.x = *reinterpret_cast<uint32_t*>(&c);
    r.y = *reinterpret_cast<uint32_t*>(&d);
    return r;
}

__global__ void __launch_bounds__(GEMM_THREADS, 1) gemm_norm_kernel(
    const float4* __restrict__ x4,
    const float4* __restrict__ W4,     // [128][64] float4 (W[c][k])
    const float*  __restrict__ bias,   // [128]
    float4*       __restrict__ out4)   // [N_NODES][32]
{
    extern __shared__ char smem[];
    const uint32_t sb = smem_u32(smem);
    const int tid  = threadIdx.x;
    const int lane = tid & 31;
    const int wid  = tid >> 5;
    const int g    = wid >> 2;     // m-group: rows g*16..+15 (0..3)
    const int qn   = wid & 3;      // n-quarter: cols qn*32..+31 (0..3)

    // Stage W -> B_hi/B_lo (once) + bias
    for (int i = tid; i < 8192; i += GEMM_THREADS) {
        int c = i >> 6, k4 = i & 63;
        float4 v = __ldg(W4 + i);
        uint32_t off = (uint32_t)(c * GSTRIDE + k4 * 8);
        *reinterpret_cast<uint2*>(smem + SM_BHI + off) = cvt_hi4(v);
        *reinterpret_cast<uint2*>(smem + SM_BLO + off) = cvt_lo4(v);
    }
    if (tid < 128) ((float*)(smem + SM_BIAS))[tid] = __ldg(bias + tid);
    __syncthreads();

    const int q = lane >> 3, r = lane & 7;
    const uint32_t aRel = (uint32_t)((g * 16 + (q & 1) * 8 + r) * GSTRIDE + (q >> 1) * 16);
    const uint32_t aHiA = sb + SM_AHI + aRel;
    const uint32_t aLoA = sb + SM_ALO + aRel;
    uint32_t bHiA[2], bLoA[2];
    #pragma unroll
    for (int p = 0; p < 2; p++) {
        uint32_t bRel = (uint32_t)((qn * 32 + p * 16 + (q >> 1) * 8 + r) * GSTRIDE + (q & 1) * 16);
        bHiA[p] = sb + SM_BHI + bRel;
        bLoA[p] = sb + SM_BLO + bRel;
    }

    float2* out2 = (float2*)out4;
    const float* bs = (const float*)(smem + SM_BIAS);
    float* snorm = (float*)(smem + SM_NORM);   // [64 rows][4 quarters]

    for (int tile = blockIdx.x; tile < NTILES; tile += GEMM_GRID) {
        const int base = tile * GEMM_ROWS;

        // ---- stage A_hi AND A_lo (single fp32 read) ----
        for (int i = tid; i < 4096; i += GEMM_THREADS) {
            int rr = i >> 6, k4 = i & 63;
            int row = base + rr;
            float4 v = make_float4(0.f, 0.f, 0.f, 0.f);
            if (row < N_NODES)
                v = (k4 < 32) ? __ldg(x4 + row * 32 + k4)
                              : g_neigh4[row * 32 + (k4 - 32)];
            uint32_t off = (uint32_t)(rr * GSTRIDE + k4 * 8);
            *reinterpret_cast<uint2*>(smem + SM_AHI + off) = cvt_hi4(v);
            *reinterpret_cast<uint2*>(smem + SM_ALO + off) = cvt_lo4(v);
        }
        __syncthreads();

        float c[4][4];
        #pragma unroll
        for (int nt = 0; nt < 4; nt++)
            #pragma unroll
            for (int j = 0; j < 4; j++) c[nt][j] = 0.f;

        // ---- single k-loop, 3 interleaved bf16 passes ----
        #pragma unroll 4
        for (int k = 0; k < 16; k++) {
            uint32_t ah[4], al[4], bh[4][2], bl[4][2];
            ldsm_x4(ah[0], ah[1], ah[2], ah[3], aHiA + k * 32);
            ldsm_x4(al[0], al[1], al[2], al[3], aLoA + k * 32);
            #pragma unroll
            for (int p = 0; p < 2; p++) {
                ldsm_x4(bh[2*p][0], bh[2*p][1], bh[2*p+1][0], bh[2*p+1][1], bHiA[p] + k * 32);
                ldsm_x4(bl[2*p][0], bl[2*p][1], bl[2*p+1][0], bl[2*p+1][1], bLoA[p] + k * 32);
            }
            #pragma unroll
            for (int nt = 0; nt < 4; nt++) {
                mma_bf16(c[nt], ah, bh[nt]);
                mma_bf16(c[nt], ah, bl[nt]);
                mma_bf16(c[nt], al, bh[nt]);
            }
        }

        // ---- epilogue 1: per-quarter partial row norms -> smem ----
        #pragma unroll
        for (int h2 = 0; h2 < 2; h2++) {
            float ss = 0.f;
            #pragma unroll
            for (int nt = 0; nt < 4; nt++) {
                int col = qn * 32 + nt * 8 + (lane & 3) * 2;
                float v0 = c[nt][2*h2 + 0] + bs[col + 0];
                float v1 = c[nt][2*h2 + 1] + bs[col + 1];
                ss += v0 * v0 + v1 * v1;
            }
            ss += __shfl_xor_sync(0xffffffffu, ss, 1);
            ss += __shfl_xor_sync(0xffffffffu, ss, 2);
            if ((lane & 3) == 0)
                snorm[(g * 16 + h2 * 8 + (lane >> 2)) * 4 + qn] = ss;
        }
        __syncthreads();

        // ---- epilogue 2: combine quarters, normalize, store ----
        #pragma unroll
        for (int h2 = 0; h2 < 2; h2++) {
            int rl = g * 16 + h2 * 8 + (lane >> 2);
            float ss = (snorm[rl * 4 + 0] + snorm[rl * 4 + 1]) +
                       (snorm[rl * 4 + 2] + snorm[rl * 4 + 3]);
            float sc = 1.0f / fmaxf(sqrtf(ss), 1e-12f);
            int row = base + rl;
            if (row < N_NODES) {
                #pragma unroll
                for (int nt = 0; nt < 4; nt++) {
                    int col = qn * 32 + nt * 8 + (lane & 3) * 2;
                    float v0 = c[nt][2*h2 + 0] + bs[col + 0];
                    float v1 = c[nt][2*h2 + 1] + bs[col + 1];
                    out2[row * 64 + qn * 16 + nt * 4 + (lane & 3)] =
                        make_float2(v0 * sc, v1 * sc);
                }
            }
        }
        __syncthreads();   // snorm/A reused next tile
    }
}

// ---------------------------------------------------------------------------
extern "C" void kernel_launch(void* const* d_in, const int* in_sizes, int n_in,
                              void* d_out, int out_size) {
    const float4*    x4   = (const float4*)d_in[0];
    const long long* ei   = (const long long*)d_in[1];
    const float4*    W4   = (const float4*)d_in[2];
    const float*     bias = (const float*)d_in[3];
    float4*          out4 = (float4*)d_out;

    cudaFuncSetAttribute(gemm_norm_kernel,
                         cudaFuncAttributeMaxDynamicSharedMemorySize, SM_TOT);

    k_edges<<<COOP_GRID, 256>>>(ei, x4);
    gemm_norm_kernel<<<GEMM_GRID, GEMM_THREADS, SM_TOT>>>(x4, W4, bias, out4);
}

// round 14
// speedup vs baseline: 1.2012x; 1.0350x over previous
#include <cuda_runtime.h>
#include <cuda_bf16.h>
#include <cstdint>

#define N_NODES 50000
#define N_EDGES 800000
#define SCAN_BLOCKS ((N_NODES + 255) / 256)   // 196 virtual scan tiles
#define COOP_GRID 296                          // 2 blocks/SM, all resident
#define GSZ (COOP_GRID * 256)
#define AGG_WARPS (COOP_GRID * 8)
#define GEMM_ROWS 64
#define NTILES ((N_NODES + GEMM_ROWS - 1) / GEMM_ROWS)   // 782
#define GEMM_GRID 148
#define GEMM_THREADS 1024

// ---- scratch (device globals; no allocs) ----
__device__ __align__(16) float4 g_neigh4[N_NODES * 32];
__device__ int g_deg_i[N_NODES];
__device__ int g_cursor[N_NODES];
__device__ int g_src_bin[N_EDGES];
__device__ int g_scan_val[SCAN_BLOCKS];
__device__ int g_ei_is64;
__device__ int g_bar_count;          // self-resets each barrier -> replay-safe
__device__ volatile int g_bar_gen;   // monotonically increasing; relative compare

// ---- dtype-agnostic edge index reads (int32 low-word: values < 50000) ----
__device__ __forceinline__ int load_src(const long long* ei, int e) {
    const int* p = (const int*)ei;
    return g_ei_is64 ? __ldg(p + 2 * e) : __ldg(p + e);
}
__device__ __forceinline__ int load_dst(const long long* ei, int e) {
    const int* p = (const int*)ei;
    return g_ei_is64 ? __ldg(p + 2 * (N_EDGES + e)) : __ldg(p + N_EDGES + e);
}

// ---- grid-wide barrier (all COOP_GRID blocks resident) ----
__device__ __forceinline__ void grid_bar() {
    __threadfence();
    __syncthreads();
    if (threadIdx.x == 0) {
        int my = g_bar_gen;
        if (atomicAdd(&g_bar_count, 1) == COOP_GRID - 1) {
            g_bar_count = 0;
            __threadfence();
            g_bar_gen = my + 1;
        } else {
            while (g_bar_gen == my) { }
            __threadfence();
        }
    }
    __syncthreads();
}

// ===========================================================================
// K1: ONE persistent kernel: zero+probe | hist | scan | binfill | aggregate
// (unchanged — measured good: ~58 us for the whole edge pipeline)
// ===========================================================================
__global__ void __launch_bounds__(256, 2) k_edges(const long long* __restrict__ ei,
                                                  const float4* __restrict__ x4) {
    __shared__ int s[256];
    __shared__ int wsum[8];
    const int tid  = threadIdx.x;
    const int gtid = blockIdx.x * 256 + tid;
    const int lane = tid & 31;

    for (int i = gtid; i < N_NODES; i += GSZ) g_deg_i[i] = 0;
    if (gtid == 0) {
        int ok = 1;
        for (int k = 0; k < 64; k++) {
            long long v = ei[k];
            if (v < 0 || v >= N_NODES) { ok = 0; break; }
        }
        g_ei_is64 = ok;
    }
    grid_bar();

    for (int e = gtid; e < N_EDGES; e += GSZ) {
        int d = load_dst(ei, e);
        if ((unsigned)d < N_NODES) atomicAdd(&g_deg_i[d], 1);
    }
    grid_bar();

    for (int vt = blockIdx.x; vt < SCAN_BLOCKS; vt += COOP_GRID) {
        int i = vt * 256 + tid;
        int v = (i < N_NODES) ? g_deg_i[i] : 0;
        #pragma unroll
        for (int o = 16; o; o >>= 1) v += __shfl_xor_sync(0xffffffffu, v, o);
        if (lane == 0) wsum[tid >> 5] = v;
        __syncthreads();
        if (tid == 0) {
            int t = 0;
            #pragma unroll
            for (int j = 0; j < 8; j++) t += wsum[j];
            g_scan_val[vt] = t;
        }
        __syncthreads();
    }
    grid_bar();

    if (blockIdx.x == 0) {
        int v = (tid < SCAN_BLOCKS) ? g_scan_val[tid] : 0;
        s[tid] = v;
        __syncthreads();
        int acc = v;
        #pragma unroll
        for (int off = 1; off < 256; off <<= 1) {
            int t = (tid >= off) ? s[tid - off] : 0;
            __syncthreads();
            acc += t;
            s[tid] = acc;
            __syncthreads();
        }
        if (tid < SCAN_BLOCKS) g_scan_val[tid] = acc - v;
    }
    grid_bar();

    for (int vt = blockIdx.x; vt < SCAN_BLOCKS; vt += COOP_GRID) {
        int i = vt * 256 + tid;
        int v = (i < N_NODES) ? g_deg_i[i] : 0;
        s[tid] = v;
        __syncthreads();
        int acc = v;
        #pragma unroll
        for (int off = 1; off < 256; off <<= 1) {
            int t = (tid >= off) ? s[tid - off] : 0;
            __syncthreads();
            acc += t;
            s[tid] = acc;
            __syncthreads();
        }
        if (i < N_NODES) g_cursor[i] = g_scan_val[vt] + acc - v;
        __syncthreads();
    }
    grid_bar();

    for (int e = gtid; e < N_EDGES; e += GSZ) {
        int sr = load_src(ei, e);
        int d  = load_dst(ei, e);
        if ((unsigned)sr >= N_NODES || (unsigned)d >= N_NODES) continue;
        int pos = atomicAdd(&g_cursor[d], 1);
        g_src_bin[pos] = sr;
    }
    grid_bar();

    for (int n = gtid >> 5; n < N_NODES; n += AGG_WARPS) {
        int end = g_cursor[n];
        int deg = g_deg_i[n];
        int beg = end - deg;

        float4 a0 = make_float4(0.f, 0.f, 0.f, 0.f);
        float4 a1 = make_float4(0.f, 0.f, 0.f, 0.f);
        float4 a2 = make_float4(0.f, 0.f, 0.f, 0.f);
        float4 a3 = make_float4(0.f, 0.f, 0.f, 0.f);

        for (int base = beg; base < end; base += 32) {
            int m = min(32, end - base);
            int sv = (base + lane < end) ? __ldg(g_src_bin + base + lane) : 0;
            int j = 0;
            for (; j + 3 < m; j += 4) {
                int s0 = __shfl_sync(0xffffffffu, sv, j);
                int s1 = __shfl_sync(0xffffffffu, sv, j + 1);
                int s2 = __shfl_sync(0xffffffffu, sv, j + 2);
                int s3 = __shfl_sync(0xffffffffu, sv, j + 3);
                float4 v0 = __ldg(x4 + s0 * 32 + lane);
                float4 v1 = __ldg(x4 + s1 * 32 + lane);
                float4 v2 = __ldg(x4 + s2 * 32 + lane);
                float4 v3 = __ldg(x4 + s3 * 32 + lane);
                a0.x += v0.x; a0.y += v0.y; a0.z += v0.z; a0.w += v0.w;
                a1.x += v1.x; a1.y += v1.y; a1.z += v1.z; a1.w += v1.w;
                a2.x += v2.x; a2.y += v2.y; a2.z += v2.z; a2.w += v2.w;
                a3.x += v3.x; a3.y += v3.y; a3.z += v3.z; a3.w += v3.w;
            }
            for (; j < m; j++) {
                int s0 = __shfl_sync(0xffffffffu, sv, j);
                float4 v0 = __ldg(x4 + s0 * 32 + lane);
                a0.x += v0.x; a0.y += v0.y; a0.z += v0.z; a0.w += v0.w;
            }
        }
        float sc = 1.0f / fmaxf((float)deg, 1.0f);
        g_neigh4[n * 32 + lane] =
            make_float4(((a0.x + a1.x) + (a2.x + a3.x)) * sc,
                        ((a0.y + a1.y) + (a2.y + a3.y)) * sc,
                        ((a0.z + a1.z) + (a2.z + a3.z)) * sc,
                        ((a0.w + a1.w) + (a2.w + a3.w)) * sc);
    }
}

// ===========================================================================
// K2: mma.sync bf16-split GEMM, 1024 THREADS (32 warps/SM; measured trend
// 8w=86us, 16w=65.7us, occ 25% -> still latency-bound, double warps again).
// 64-row tiles; A_hi+A_lo staged once; interleaved 3-pass k-loop.
// 32 warps = 4 m-groups x 8 n-eighths; warp tile 16x16; per k: 4 LDSM.x4
// -> 6 HMMA; c[2][4] = 8 regs. Row norm combined across 8 slices in smem.
// ===========================================================================
#define GSTRIDE 528
#define SM_BIAS  0                               // 512 B
#define SM_NORM  512                             // 64 rows x 8 slices = 2048 B
#define SM_AHI   2560
#define SM_ALO   (SM_AHI + 64 * GSTRIDE)
#define SM_BHI   (SM_ALO + 64 * GSTRIDE)
#define SM_BLO   (SM_BHI + 128 * GSTRIDE)
#define SM_TOT   (SM_BLO + 128 * GSTRIDE)        // 205312 B

__device__ __forceinline__ uint32_t smem_u32(const void* p) {
    uint32_t a;
    asm("{ .reg .u64 t; cvta.to.shared.u64 t, %1; cvt.u32.u64 %0, t; }" : "=r"(a) : "l"(p));
    return a;
}
__device__ __forceinline__ void ldsm_x4(uint32_t& r0, uint32_t& r1, uint32_t& r2,
                                        uint32_t& r3, uint32_t addr) {
    asm volatile("ldmatrix.sync.aligned.m8n8.x4.shared.b16 {%0,%1,%2,%3}, [%4];"
                 : "=r"(r0), "=r"(r1), "=r"(r2), "=r"(r3) : "r"(addr));
}
__device__ __forceinline__ void mma_bf16(float* c, const uint32_t* a, const uint32_t* b) {
    asm volatile(
        "mma.sync.aligned.m16n8k16.row.col.f32.bf16.bf16.f32 "
        "{%0,%1,%2,%3}, {%4,%5,%6,%7}, {%8,%9}, {%0,%1,%2,%3};"
        : "+f"(c[0]), "+f"(c[1]), "+f"(c[2]), "+f"(c[3])
        : "r"(a[0]), "r"(a[1]), "r"(a[2]), "r"(a[3]), "r"(b[0]), "r"(b[1]));
}
__device__ __forceinline__ uint2 cvt_hi4(float4 v) {
    __nv_bfloat162 a = __floats2bfloat162_rn(v.x, v.y);
    __nv_bfloat162 b = __floats2bfloat162_rn(v.z, v.w);
    uint2 r;
    r.x = *reinterpret_cast<uint32_t*>(&a);
    r.y = *reinterpret_cast<uint32_t*>(&b);
    return r;
}
__device__ __forceinline__ uint2 cvt_lo4(float4 v) {
    __nv_bfloat162 a = __floats2bfloat162_rn(v.x, v.y);
    __nv_bfloat162 b = __floats2bfloat162_rn(v.z, v.w);
    float4 l = make_float4(v.x - __bfloat162float(a.x), v.y - __bfloat162float(a.y),
                           v.z - __bfloat162float(b.x), v.w - __bfloat162float(b.y));
    __nv_bfloat162 c = __floats2bfloat162_rn(l.x, l.y);
    __nv_bfloat162 d = __floats2bfloat162_rn(l.z, l.w);
    uint2 r;
    r.x = *reinterpret_cast<uint32_t*>(&c);
    r.y = *reinterpret_cast<uint32_t*>(&d);
    return r;
}

__global__ void __launch_bounds__(GEMM_THREADS, 1) gemm_norm_kernel(
    const float4* __restrict__ x4,
    const float4* __restrict__ W4,     // [128][64] float4 (W[c][k])
    const float*  __restrict__ bias,   // [128]
    float4*       __restrict__ out4)   // [N_NODES][32]
{
    extern __shared__ char smem[];
    const uint32_t sb = smem_u32(smem);
    const int tid  = threadIdx.x;
    const int lane = tid & 31;
    const int wid  = tid >> 5;
    const int g    = wid >> 3;     // m-group: rows g*16..+15 (0..3)
    const int qn   = wid & 7;      // n-eighth: cols qn*16..+15 (0..7)

    // Stage W -> B_hi/B_lo (once) + bias
    for (int i = tid; i < 8192; i += GEMM_THREADS) {
        int c = i >> 6, k4 = i & 63;
        float4 v = __ldg(W4 + i);
        uint32_t off = (uint32_t)(c * GSTRIDE + k4 * 8);
        *reinterpret_cast<uint2*>(smem + SM_BHI + off) = cvt_hi4(v);
        *reinterpret_cast<uint2*>(smem + SM_BLO + off) = cvt_lo4(v);
    }
    if (tid < 128) ((float*)(smem + SM_BIAS))[tid] = __ldg(bias + tid);
    __syncthreads();

    const int q = lane >> 3, r = lane & 7;
    const uint32_t aRel = (uint32_t)((g * 16 + (q & 1) * 8 + r) * GSTRIDE + (q >> 1) * 16);
    const uint32_t aHiA = sb + SM_AHI + aRel;
    const uint32_t aLoA = sb + SM_ALO + aRel;
    // B x4 covers both n-tiles of the warp's 16 cols:
    // matrices = (n0-7,k0-7)(n0-7,k8-15)(n8-15,k0-7)(n8-15,k8-15)
    const uint32_t bRel = (uint32_t)((qn * 16 + (q >> 1) * 8 + r) * GSTRIDE + (q & 1) * 16);
    const uint32_t bHiA = sb + SM_BHI + bRel;
    const uint32_t bLoA = sb + SM_BLO + bRel;

    float2* out2 = (float2*)out4;
    const float* bs = (const float*)(smem + SM_BIAS);
    float* snorm = (float*)(smem + SM_NORM);   // [64 rows][8 slices]

    for (int tile = blockIdx.x; tile < NTILES; tile += GEMM_GRID) {
        const int base = tile * GEMM_ROWS;

        // ---- stage A_hi AND A_lo (single fp32 read) ----
        for (int i = tid; i < 4096; i += GEMM_THREADS) {
            int rr = i >> 6, k4 = i & 63;
            int row = base + rr;
            float4 v = make_float4(0.f, 0.f, 0.f, 0.f);
            if (row < N_NODES)
                v = (k4 < 32) ? __ldg(x4 + row * 32 + k4)
                              : g_neigh4[row * 32 + (k4 - 32)];
            uint32_t off = (uint32_t)(rr * GSTRIDE + k4 * 8);
            *reinterpret_cast<uint2*>(smem + SM_AHI + off) = cvt_hi4(v);
            *reinterpret_cast<uint2*>(smem + SM_ALO + off) = cvt_lo4(v);
        }
        __syncthreads();

        float c[2][4];
        #pragma unroll
        for (int nt = 0; nt < 2; nt++)
            #pragma unroll
            for (int j = 0; j < 4; j++) c[nt][j] = 0.f;

        // ---- single k-loop, 3 interleaved bf16 passes ----
        #pragma unroll 4
        for (int k = 0; k < 16; k++) {
            uint32_t ah[4], al[4], bh[2][2], bl[2][2];
            ldsm_x4(ah[0], ah[1], ah[2], ah[3], aHiA + k * 32);
            ldsm_x4(al[0], al[1], al[2], al[3], aLoA + k * 32);
            ldsm_x4(bh[0][0], bh[0][1], bh[1][0], bh[1][1], bHiA + k * 32);
            ldsm_x4(bl[0][0], bl[0][1], bl[1][0], bl[1][1], bLoA + k * 32);
            #pragma unroll
            for (int nt = 0; nt < 2; nt++) {
                mma_bf16(c[nt], ah, bh[nt]);
                mma_bf16(c[nt], ah, bl[nt]);
                mma_bf16(c[nt], al, bh[nt]);
            }
        }

        // ---- epilogue 1: per-slice partial row norms -> smem ----
        #pragma unroll
        for (int h2 = 0; h2 < 2; h2++) {
            float ss = 0.f;
            #pragma unroll
            for (int nt = 0; nt < 2; nt++) {
                int col = qn * 16 + nt * 8 + (lane & 3) * 2;
                float v0 = c[nt][2*h2 + 0] + bs[col + 0];
                float v1 = c[nt][2*h2 + 1] + bs[col + 1];
                ss += v0 * v0 + v1 * v1;
            }
            ss += __shfl_xor_sync(0xffffffffu, ss, 1);
            ss += __shfl_xor_sync(0xffffffffu, ss, 2);
            if ((lane & 3) == 0)
                snorm[(g * 16 + h2 * 8 + (lane >> 2)) * 8 + qn] = ss;
        }
        __syncthreads();

        // ---- epilogue 2: combine slices, normalize, store ----
        #pragma unroll
        for (int h2 = 0; h2 < 2; h2++) {
            int rl = g * 16 + h2 * 8 + (lane >> 2);
            float ss = ((snorm[rl*8+0] + snorm[rl*8+1]) + (snorm[rl*8+2] + snorm[rl*8+3]))
                     + ((snorm[rl*8+4] + snorm[rl*8+5]) + (snorm[rl*8+6] + snorm[rl*8+7]));
            float sc = 1.0f / fmaxf(sqrtf(ss), 1e-12f);
            int row = base + rl;
            if (row < N_NODES) {
                #pragma unroll
                for (int nt = 0; nt < 2; nt++) {
                    int col = qn * 16 + nt * 8 + (lane & 3) * 2;
                    float v0 = c[nt][2*h2 + 0] + bs[col + 0];
                    float v1 = c[nt][2*h2 + 1] + bs[col + 1];
                    out2[row * 64 + qn * 8 + nt * 4 + (lane & 3)] =
                        make_float2(v0 * sc, v1 * sc);
                }
            }
        }
        __syncthreads();   // snorm/A reused next tile
    }
}

// ---------------------------------------------------------------------------
extern "C" void kernel_launch(void* const* d_in, const int* in_sizes, int n_in,
                              void* d_out, int out_size) {
    const float4*    x4   = (const float4*)d_in[0];
    const long long* ei   = (const long long*)d_in[1];
    const float4*    W4   = (const float4*)d_in[2];
    const float*     bias = (const float*)d_in[3];
    float4*          out4 = (float4*)d_out;

    cudaFuncSetAttribute(gemm_norm_kernel,
                         cudaFuncAttributeMaxDynamicSharedMemorySize, SM_TOT);

    k_edges<<<COOP_GRID, 256>>>(ei, x4);
    gemm_norm_kernel<<<GEMM_GRID, GEMM_THREADS, SM_TOT>>>(x4, W4, bias, out4);
}

// round 15
// speedup vs baseline: 1.2175x; 1.0136x over previous
#include <cuda_runtime.h>
#include <cuda_bf16.h>
#include <cstdint>

#define N_NODES 50000
#define N_EDGES 800000
#define COOP_GRID 148
#define THREADS 1024
#define GSZ (COOP_GRID * THREADS)
#define AGG_WARPS (COOP_GRID * 32)
#define SCAN_TILE 1024
#define SCAN_TILES ((N_NODES + SCAN_TILE - 1) / SCAN_TILE)   // 49
#define GEMM_ROWS 64
#define NTILES ((N_NODES + GEMM_ROWS - 1) / GEMM_ROWS)       // 782

// ---- scratch (device globals; no allocs) ----
__device__ __align__(16) float4 g_neigh4[N_NODES * 32];
__device__ int g_deg_i[N_NODES];
__device__ int g_cursor[N_NODES];
__device__ int g_src_bin[N_EDGES];
__device__ int g_scan_val[SCAN_TILES];
__device__ int g_ei_is64;
__device__ int g_bar_count;          // self-resets each barrier -> replay-safe
__device__ volatile int g_bar_gen;   // monotonically increasing; relative compare

// ---- smem layout (205 KB) ----
#define GSTRIDE 528
#define SM_BIAS  0                               // 512 B
#define SM_NORM  512                             // 64 rows x 8 slices = 2048 B
#define SM_AHI   2560                            // also scan scratch pre-gemm
#define SM_ALO   (SM_AHI + 64 * GSTRIDE)
#define SM_BHI   (SM_ALO + 64 * GSTRIDE)
#define SM_BLO   (SM_BHI + 128 * GSTRIDE)
#define SM_TOT   (SM_BLO + 128 * GSTRIDE)        // 205312 B

// ---- dtype-agnostic edge index reads (int32 low-word: values < 50000) ----
__device__ __forceinline__ int load_src(const long long* ei, int e) {
    const int* p = (const int*)ei;
    return g_ei_is64 ? __ldg(p + 2 * e) : __ldg(p + e);
}
__device__ __forceinline__ int load_dst(const long long* ei, int e) {
    const int* p = (const int*)ei;
    return g_ei_is64 ? __ldg(p + 2 * (N_EDGES + e)) : __ldg(p + N_EDGES + e);
}

// ---- grid-wide barrier (all COOP_GRID blocks resident) ----
__device__ __forceinline__ void grid_bar() {
    __threadfence();
    __syncthreads();
    if (threadIdx.x == 0) {
        int my = g_bar_gen;
        if (atomicAdd(&g_bar_count, 1) == COOP_GRID - 1) {
            g_bar_count = 0;
            __threadfence();
            g_bar_gen = my + 1;
        } else {
            while (g_bar_gen == my) { }
            __threadfence();
        }
    }
    __syncthreads();
}

__device__ __forceinline__ uint32_t smem_u32(const void* p) {
    uint32_t a;
    asm("{ .reg .u64 t; cvta.to.shared.u64 t, %1; cvt.u32.u64 %0, t; }" : "=r"(a) : "l"(p));
    return a;
}
__device__ __forceinline__ void ldsm_x4(uint32_t& r0, uint32_t& r1, uint32_t& r2,
                                        uint32_t& r3, uint32_t addr) {
    asm volatile("ldmatrix.sync.aligned.m8n8.x4.shared.b16 {%0,%1,%2,%3}, [%4];"
                 : "=r"(r0), "=r"(r1), "=r"(r2), "=r"(r3) : "r"(addr));
}
__device__ __forceinline__ void mma_bf16(float* c, const uint32_t* a, const uint32_t* b) {
    asm volatile(
        "mma.sync.aligned.m16n8k16.row.col.f32.bf16.bf16.f32 "
        "{%0,%1,%2,%3}, {%4,%5,%6,%7}, {%8,%9}, {%0,%1,%2,%3};"
        : "+f"(c[0]), "+f"(c[1]), "+f"(c[2]), "+f"(c[3])
        : "r"(a[0]), "r"(a[1]), "r"(a[2]), "r"(a[3]), "r"(b[0]), "r"(b[1]));
}
__device__ __forceinline__ uint2 cvt_hi4(float4 v) {
    __nv_bfloat162 a = __floats2bfloat162_rn(v.x, v.y);
    __nv_bfloat162 b = __floats2bfloat162_rn(v.z, v.w);
    uint2 r;
    r.x = *reinterpret_cast<uint32_t*>(&a);
    r.y = *reinterpret_cast<uint32_t*>(&b);
    return r;
}
__device__ __forceinline__ uint2 cvt_lo4(float4 v) {
    __nv_bfloat162 a = __floats2bfloat162_rn(v.x, v.y);
    __nv_bfloat162 b = __floats2bfloat162_rn(v.z, v.w);
    float4 l = make_float4(v.x - __bfloat162float(a.x), v.y - __bfloat162float(a.y),
                           v.z - __bfloat162float(b.x), v.w - __bfloat162float(b.y));
    __nv_bfloat162 c = __floats2bfloat162_rn(l.x, l.y);
    __nv_bfloat162 d = __floats2bfloat162_rn(l.z, l.w);
    uint2 r;
    r.x = *reinterpret_cast<uint32_t*>(&c);
    r.y = *reinterpret_cast<uint32_t*>(&d);
    return r;
}

// ===========================================================================
// THE kernel: W-stage | zero+probe | hist | scan | binfill | aggregate | GEMM
// 148 blocks x 1024 threads, 205 KB smem, all resident (grid_bar-safe).
// ===========================================================================
__global__ void __launch_bounds__(THREADS, 1) k_fused(
    const long long* __restrict__ ei,
    const float4*    __restrict__ x4,
    const float4*    __restrict__ W4,     // [128][64] float4 (W[c][k])
    const float*     __restrict__ bias,   // [128]
    float4*          __restrict__ out4)   // [N_NODES][32]
{
    extern __shared__ char smem[];
    const uint32_t sb = smem_u32(smem);
    const int tid  = threadIdx.x;
    const int lane = tid & 31;
    const int wid  = tid >> 5;
    const int gtid = blockIdx.x * THREADS + tid;

    int* s_scan = (int*)(smem + SM_AHI);          // scan scratch (pre-gemm only)
    int* s_ws   = s_scan + SCAN_TILE;             // 32 warp sums

    // ---- phase W: stage W -> B_hi/B_lo + bias (persist across all phases) ----
    for (int i = tid; i < 8192; i += THREADS) {
        int c = i >> 6, k4 = i & 63;
        float4 v = __ldg(W4 + i);
        uint32_t off = (uint32_t)(c * GSTRIDE + k4 * 8);
        *reinterpret_cast<uint2*>(smem + SM_BHI + off) = cvt_hi4(v);
        *reinterpret_cast<uint2*>(smem + SM_BLO + off) = cvt_lo4(v);
    }
    if (tid < 128) ((float*)(smem + SM_BIAS))[tid] = __ldg(bias + tid);

    // ---- phase 0: zero counters + dtype probe ----
    for (int i = gtid; i < N_NODES; i += GSZ) g_deg_i[i] = 0;
    if (gtid == 0) {
        int ok = 1;
        for (int k = 0; k < 64; k++) {
            long long v = ei[k];
            if (v < 0 || v >= N_NODES) { ok = 0; break; }
        }
        g_ei_is64 = ok;
    }
    grid_bar();

    // ---- phase 1: in-degree histogram ----
    for (int e = gtid; e < N_EDGES; e += GSZ) {
        int d = load_dst(ei, e);
        if ((unsigned)d < N_NODES) atomicAdd(&g_deg_i[d], 1);
    }
    grid_bar();

    // ---- phase 2a: per-tile (1024) sums ----
    for (int vt = blockIdx.x; vt < SCAN_TILES; vt += COOP_GRID) {
        int i = vt * SCAN_TILE + tid;
        int v = (i < N_NODES) ? g_deg_i[i] : 0;
        #pragma unroll
        for (int o = 16; o; o >>= 1) v += __shfl_xor_sync(0xffffffffu, v, o);
        if (lane == 0) s_ws[wid] = v;
        __syncthreads();
        if (tid == 0) {
            int t = 0;
            #pragma unroll
            for (int j = 0; j < 32; j++) t += s_ws[j];
            g_scan_val[vt] = t;
        }
        __syncthreads();
    }
    grid_bar();

    // ---- phase 2b: block 0 exclusive-scans the 49 tile sums ----
    if (blockIdx.x == 0) {
        int v = (tid < SCAN_TILES) ? g_scan_val[tid] : 0;
        if (tid < 64) s_scan[tid] = v;
        __syncthreads();
        int acc = v;
        #pragma unroll
        for (int off = 1; off < 64; off <<= 1) {
            int t = (tid >= off && tid < 64) ? s_scan[tid - off] : 0;
            __syncthreads();
            if (tid < 64) { acc += t; s_scan[tid] = acc; }
            __syncthreads();
        }
        if (tid < SCAN_TILES) g_scan_val[tid] = acc - v;
    }
    grid_bar();

    // ---- phase 2c: per-tile exclusive scan (1024) + base -> cursor ----
    for (int vt = blockIdx.x; vt < SCAN_TILES; vt += COOP_GRID) {
        int i = vt * SCAN_TILE + tid;
        int v = (i < N_NODES) ? g_deg_i[i] : 0;
        s_scan[tid] = v;
        __syncthreads();
        int acc = v;
        #pragma unroll
        for (int off = 1; off < SCAN_TILE; off <<= 1) {
            int t = (tid >= off) ? s_scan[tid - off] : 0;
            __syncthreads();
            acc += t;
            s_scan[tid] = acc;
            __syncthreads();
        }
        if (i < N_NODES) g_cursor[i] = g_scan_val[vt] + acc - v;
        __syncthreads();
    }
    grid_bar();

    // ---- phase 3: bin fill ----
    for (int e = gtid; e < N_EDGES; e += GSZ) {
        int sr = load_src(ei, e);
        int d  = load_dst(ei, e);
        if ((unsigned)sr >= N_NODES || (unsigned)d >= N_NODES) continue;
        int pos = atomicAdd(&g_cursor[d], 1);
        g_src_bin[pos] = sr;
    }
    grid_bar();

    // ---- phase 4: gather-aggregate (warp/node, 4-way MLP unroll) ----
    for (int n = gtid >> 5; n < N_NODES; n += AGG_WARPS) {
        int end = g_cursor[n];
        int deg = g_deg_i[n];
        int beg = end - deg;

        float4 a0 = make_float4(0.f, 0.f, 0.f, 0.f);
        float4 a1 = make_float4(0.f, 0.f, 0.f, 0.f);
        float4 a2 = make_float4(0.f, 0.f, 0.f, 0.f);
        float4 a3 = make_float4(0.f, 0.f, 0.f, 0.f);

        for (int base = beg; base < end; base += 32) {
            int m = min(32, end - base);
            int sv = (base + lane < end) ? __ldg(g_src_bin + base + lane) : 0;
            int j = 0;
            for (; j + 3 < m; j += 4) {
                int s0 = __shfl_sync(0xffffffffu, sv, j);
                int s1 = __shfl_sync(0xffffffffu, sv, j + 1);
                int s2 = __shfl_sync(0xffffffffu, sv, j + 2);
                int s3 = __shfl_sync(0xffffffffu, sv, j + 3);
                float4 v0 = __ldg(x4 + s0 * 32 + lane);
                float4 v1 = __ldg(x4 + s1 * 32 + lane);
                float4 v2 = __ldg(x4 + s2 * 32 + lane);
                float4 v3 = __ldg(x4 + s3 * 32 + lane);
                a0.x += v0.x; a0.y += v0.y; a0.z += v0.z; a0.w += v0.w;
                a1.x += v1.x; a1.y += v1.y; a1.z += v1.z; a1.w += v1.w;
                a2.x += v2.x; a2.y += v2.y; a2.z += v2.z; a2.w += v2.w;
                a3.x += v3.x; a3.y += v3.y; a3.z += v3.z; a3.w += v3.w;
            }
            for (; j < m; j++) {
                int s0 = __shfl_sync(0xffffffffu, sv, j);
                float4 v0 = __ldg(x4 + s0 * 32 + lane);
                a0.x += v0.x; a0.y += v0.y; a0.z += v0.z; a0.w += v0.w;
            }
        }
        float sc = 1.0f / fmaxf((float)deg, 1.0f);
        g_neigh4[n * 32 + lane] =
            make_float4(((a0.x + a1.x) + (a2.x + a3.x)) * sc,
                        ((a0.y + a1.y) + (a2.y + a3.y)) * sc,
                        ((a0.z + a1.z) + (a2.z + a3.z)) * sc,
                        ((a0.w + a1.w) + (a2.w + a3.w)) * sc);
    }
    grid_bar();   // aggregate done everywhere; scan scratch free -> A region

    // ---- phase 5: GEMM + bias + row L2-normalize (R14 tiling, 32 warps) ----
    const int g  = wid >> 3;     // m-group: rows g*16..+15 (0..3)
    const int qn = wid & 7;      // n-eighth: cols qn*16..+15 (0..7)

    const int q = lane >> 3, r = lane & 7;
    const uint32_t aRel = (uint32_t)((g * 16 + (q & 1) * 8 + r) * GSTRIDE + (q >> 1) * 16);
    const uint32_t aHiA = sb + SM_AHI + aRel;
    const uint32_t aLoA = sb + SM_ALO + aRel;
    const uint32_t bRel = (uint32_t)((qn * 16 + (q >> 1) * 8 + r) * GSTRIDE + (q & 1) * 16);
    const uint32_t bHiA = sb + SM_BHI + bRel;
    const uint32_t bLoA = sb + SM_BLO + bRel;

    float2* out2 = (float2*)out4;
    const float* bs = (const float*)(smem + SM_BIAS);
    float* snorm = (float*)(smem + SM_NORM);   // [64 rows][8 slices]

    for (int tile = blockIdx.x; tile < NTILES; tile += COOP_GRID) {
        const int base = tile * GEMM_ROWS;

        for (int i = tid; i < 4096; i += THREADS) {
            int rr = i >> 6, k4 = i & 63;
            int row = base + rr;
            float4 v = make_float4(0.f, 0.f, 0.f, 0.f);
            if (row < N_NODES)
                v = (k4 < 32) ? __ldg(x4 + row * 32 + k4)
                              : g_neigh4[row * 32 + (k4 - 32)];
            uint32_t off = (uint32_t)(rr * GSTRIDE + k4 * 8);
            *reinterpret_cast<uint2*>(smem + SM_AHI + off) = cvt_hi4(v);
            *reinterpret_cast<uint2*>(smem + SM_ALO + off) = cvt_lo4(v);
        }
        __syncthreads();

        float c[2][4];
        #pragma unroll
        for (int nt = 0; nt < 2; nt++)
            #pragma unroll
            for (int j = 0; j < 4; j++) c[nt][j] = 0.f;

        #pragma unroll 4
        for (int k = 0; k < 16; k++) {
            uint32_t ah[4], al[4], bh[2][2], bl[2][2];
            ldsm_x4(ah[0], ah[1], ah[2], ah[3], aHiA + k * 32);
            ldsm_x4(al[0], al[1], al[2], al[3], aLoA + k * 32);
            ldsm_x4(bh[0][0], bh[0][1], bh[1][0], bh[1][1], bHiA + k * 32);
            ldsm_x4(bl[0][0], bl[0][1], bl[1][0], bl[1][1], bLoA + k * 32);
            #pragma unroll
            for (int nt = 0; nt < 2; nt++) {
                mma_bf16(c[nt], ah, bh[nt]);
                mma_bf16(c[nt], ah, bl[nt]);
                mma_bf16(c[nt], al, bh[nt]);
            }
        }

        #pragma unroll
        for (int h2 = 0; h2 < 2; h2++) {
            float ss = 0.f;
            #pragma unroll
            for (int nt = 0; nt < 2; nt++) {
                int col = qn * 16 + nt * 8 + (lane & 3) * 2;
                float v0 = c[nt][2*h2 + 0] + bs[col + 0];
                float v1 = c[nt][2*h2 + 1] + bs[col + 1];
                ss += v0 * v0 + v1 * v1;
            }
            ss += __shfl_xor_sync(0xffffffffu, ss, 1);
            ss += __shfl_xor_sync(0xffffffffu, ss, 2);
            if ((lane & 3) == 0)
                snorm[(g * 16 + h2 * 8 + (lane >> 2)) * 8 + qn] = ss;
        }
        __syncthreads();

        #pragma unroll
        for (int h2 = 0; h2 < 2; h2++) {
            int rl = g * 16 + h2 * 8 + (lane >> 2);
            float ss = ((snorm[rl*8+0] + snorm[rl*8+1]) + (snorm[rl*8+2] + snorm[rl*8+3]))
                     + ((snorm[rl*8+4] + snorm[rl*8+5]) + (snorm[rl*8+6] + snorm[rl*8+7]));
            float sc = 1.0f / fmaxf(sqrtf(ss), 1e-12f);
            int row = base + rl;
            if (row < N_NODES) {
                #pragma unroll
                for (int nt = 0; nt < 2; nt++) {
                    int col = qn * 16 + nt * 8 + (lane & 3) * 2;
                    float v0 = c[nt][2*h2 + 0] + bs[col + 0];
                    float v1 = c[nt][2*h2 + 1] + bs[col + 1];
                    out2[row * 64 + qn * 8 + nt * 4 + (lane & 3)] =
                        make_float2(v0 * sc, v1 * sc);
                }
            }
        }
        __syncthreads();   // snorm/A reused next tile
    }
}

// ---------------------------------------------------------------------------
extern "C" void kernel_launch(void* const* d_in, const int* in_sizes, int n_in,
                              void* d_out, int out_size) {
    const float4*    x4   = (const float4*)d_in[0];
    const long long* ei   = (const long long*)d_in[1];
    const float4*    W4   = (const float4*)d_in[2];
    const float*     bias = (const float*)d_in[3];
    float4*          out4 = (float4*)d_out;

    cudaFuncSetAttribute(k_fused,
                         cudaFuncAttributeMaxDynamicSharedMemorySize, SM_TOT);

    k_fused<<<COOP_GRID, THREADS, SM_TOT>>>(ei, x4, W4, bias, out4);
}

// round 16
// speedup vs baseline: 1.2836x; 1.0543x over previous
#include <cuda_runtime.h>
#include <cuda_bf16.h>
#include <cstdint>

#define N_NODES 50000
#define N_EDGES 800000
#define COOP_GRID 148
#define THREADS 1024
#define GSZ (COOP_GRID * THREADS)
#define SCAN_TILE 1024
#define SCAN_TILES ((N_NODES + SCAN_TILE - 1) / SCAN_TILE)   // 49
#define GEMM_ROWS 64
#define NTILES ((N_NODES + GEMM_ROWS - 1) / GEMM_ROWS)       // 782

// ---- scratch (device globals; no allocs) ----
__device__ int g_deg_i[N_NODES];
__device__ int g_cursor[N_NODES];
__device__ int g_src_bin[N_EDGES];
__device__ int g_scan_val[SCAN_TILES];
__device__ int g_ei_is64;
__device__ int g_bar_count;          // self-resets each barrier -> replay-safe
__device__ volatile int g_bar_gen;   // monotonically increasing; relative compare

// ---- smem layout (205 KB) ----
#define GSTRIDE 528
#define SM_BIAS  0                               // 512 B
#define SM_NORM  512                             // 64 rows x 8 slices = 2048 B
#define SM_AHI   2560                            // also scan scratch pre-gemm
#define SM_ALO   (SM_AHI + 64 * GSTRIDE)
#define SM_BHI   (SM_ALO + 64 * GSTRIDE)
#define SM_BLO   (SM_BHI + 128 * GSTRIDE)
#define SM_TOT   (SM_BLO + 128 * GSTRIDE)        // 205312 B

// ---- dtype-agnostic edge index reads (int32 low-word: values < 50000) ----
__device__ __forceinline__ int load_src(const long long* ei, int e) {
    const int* p = (const int*)ei;
    return g_ei_is64 ? __ldg(p + 2 * e) : __ldg(p + e);
}
__device__ __forceinline__ int load_dst(const long long* ei, int e) {
    const int* p = (const int*)ei;
    return g_ei_is64 ? __ldg(p + 2 * (N_EDGES + e)) : __ldg(p + N_EDGES + e);
}

// ---- grid-wide barrier (all COOP_GRID blocks resident) ----
__device__ __forceinline__ void grid_bar() {
    __threadfence();
    __syncthreads();
    if (threadIdx.x == 0) {
        int my = g_bar_gen;
        if (atomicAdd(&g_bar_count, 1) == COOP_GRID - 1) {
            g_bar_count = 0;
            __threadfence();
            g_bar_gen = my + 1;
        } else {
            while (g_bar_gen == my) { }
            __threadfence();
        }
    }
    __syncthreads();
}

__device__ __forceinline__ uint32_t smem_u32(const void* p) {
    uint32_t a;
    asm("{ .reg .u64 t; cvta.to.shared.u64 t, %1; cvt.u32.u64 %0, t; }" : "=r"(a) : "l"(p));
    return a;
}
__device__ __forceinline__ void ldsm_x4(uint32_t& r0, uint32_t& r1, uint32_t& r2,
                                        uint32_t& r3, uint32_t addr) {
    asm volatile("ldmatrix.sync.aligned.m8n8.x4.shared.b16 {%0,%1,%2,%3}, [%4];"
                 : "=r"(r0), "=r"(r1), "=r"(r2), "=r"(r3) : "r"(addr));
}
__device__ __forceinline__ void mma_bf16(float* c, const uint32_t* a, const uint32_t* b) {
    asm volatile(
        "mma.sync.aligned.m16n8k16.row.col.f32.bf16.bf16.f32 "
        "{%0,%1,%2,%3}, {%4,%5,%6,%7}, {%8,%9}, {%0,%1,%2,%3};"
        : "+f"(c[0]), "+f"(c[1]), "+f"(c[2]), "+f"(c[3])
        : "r"(a[0]), "r"(a[1]), "r"(a[2]), "r"(a[3]), "r"(b[0]), "r"(b[1]));
}
__device__ __forceinline__ uint2 cvt_hi4(float4 v) {
    __nv_bfloat162 a = __floats2bfloat162_rn(v.x, v.y);
    __nv_bfloat162 b = __floats2bfloat162_rn(v.z, v.w);
    uint2 r;
    r.x = *reinterpret_cast<uint32_t*>(&a);
    r.y = *reinterpret_cast<uint32_t*>(&b);
    return r;
}
__device__ __forceinline__ uint2 cvt_lo4(float4 v) {
    __nv_bfloat162 a = __floats2bfloat162_rn(v.x, v.y);
    __nv_bfloat162 b = __floats2bfloat162_rn(v.z, v.w);
    float4 l = make_float4(v.x - __bfloat162float(a.x), v.y - __bfloat162float(a.y),
                           v.z - __bfloat162float(b.x), v.w - __bfloat162float(b.y));
    __nv_bfloat162 c = __floats2bfloat162_rn(l.x, l.y);
    __nv_bfloat162 d = __floats2bfloat162_rn(l.z, l.w);
    uint2 r;
    r.x = *reinterpret_cast<uint32_t*>(&c);
    r.y = *reinterpret_cast<uint32_t*>(&d);
    return r;
}

// ===========================================================================
// THE kernel. Phases: W-stage | zero+probe | hist | scan | binfill (4 bars)
// then per-owned-tile: {warp-gather neigh -> smem A directly (no global
// round-trip), stage x half, bf16-split MMA mainloop, bias+L2-norm epilogue}.
// Block b owns tiles b, b+148, ... so aggregate->gemm needs NO grid_bar.
// ===========================================================================
__global__ void __launch_bounds__(THREADS, 1) k_fused(
    const long long* __restrict__ ei,
    const float4*    __restrict__ x4,
    const float4*    __restrict__ W4,     // [128][64] float4 (W[c][k])
    const float*     __restrict__ bias,   // [128]
    float4*          __restrict__ out4)   // [N_NODES][32]
{
    extern __shared__ char smem[];
    const uint32_t sb = smem_u32(smem);
    const int tid  = threadIdx.x;
    const int lane = tid & 31;
    const int wid  = tid >> 5;
    const int gtid = blockIdx.x * THREADS + tid;

    int* s_scan = (int*)(smem + SM_AHI);          // scan scratch (pre-gemm only)
    int* s_ws   = s_scan + SCAN_TILE;             // 32 warp sums

    // ---- phase W: stage W -> B_hi/B_lo + bias (persist across all phases) ----
    for (int i = tid; i < 8192; i += THREADS) {
        int c = i >> 6, k4 = i & 63;
        float4 v = __ldg(W4 + i);
        uint32_t off = (uint32_t)(c * GSTRIDE + k4 * 8);
        *reinterpret_cast<uint2*>(smem + SM_BHI + off) = cvt_hi4(v);
        *reinterpret_cast<uint2*>(smem + SM_BLO + off) = cvt_lo4(v);
    }
    if (tid < 128) ((float*)(smem + SM_BIAS))[tid] = __ldg(bias + tid);

    // ---- phase 0: zero counters + dtype probe ----
    for (int i = gtid; i < N_NODES; i += GSZ) g_deg_i[i] = 0;
    if (gtid == 0) {
        int ok = 1;
        for (int k = 0; k < 64; k++) {
            long long v = ei[k];
            if (v < 0 || v >= N_NODES) { ok = 0; break; }
        }
        g_ei_is64 = ok;
    }
    grid_bar();

    // ---- phase 1: in-degree histogram ----
    for (int e = gtid; e < N_EDGES; e += GSZ) {
        int d = load_dst(ei, e);
        if ((unsigned)d < N_NODES) atomicAdd(&g_deg_i[d], 1);
    }
    grid_bar();

    // ---- phase 2a: per-tile (1024) sums ----
    for (int vt = blockIdx.x; vt < SCAN_TILES; vt += COOP_GRID) {
        int i = vt * SCAN_TILE + tid;
        int v = (i < N_NODES) ? g_deg_i[i] : 0;
        #pragma unroll
        for (int o = 16; o; o >>= 1) v += __shfl_xor_sync(0xffffffffu, v, o);
        if (lane == 0) s_ws[wid] = v;
        __syncthreads();
        if (tid == 0) {
            int t = 0;
            #pragma unroll
            for (int j = 0; j < 32; j++) t += s_ws[j];
            g_scan_val[vt] = t;
        }
        __syncthreads();
    }
    grid_bar();

    // ---- phase 2b: block 0 exclusive-scans the 49 tile sums ----
    if (blockIdx.x == 0) {
        int v = (tid < SCAN_TILES) ? g_scan_val[tid] : 0;
        if (tid < 64) s_scan[tid] = v;
        __syncthreads();
        int acc = v;
        #pragma unroll
        for (int off = 1; off < 64; off <<= 1) {
            int t = (tid >= off && tid < 64) ? s_scan[tid - off] : 0;
            __syncthreads();
            if (tid < 64) { acc += t; s_scan[tid] = acc; }
            __syncthreads();
        }
        if (tid < SCAN_TILES) g_scan_val[tid] = acc - v;
    }
    grid_bar();

    // ---- phase 2c: per-tile exclusive scan (1024) + base -> cursor ----
    for (int vt = blockIdx.x; vt < SCAN_TILES; vt += COOP_GRID) {
        int i = vt * SCAN_TILE + tid;
        int v = (i < N_NODES) ? g_deg_i[i] : 0;
        s_scan[tid] = v;
        __syncthreads();
        int acc = v;
        #pragma unroll
        for (int off = 1; off < SCAN_TILE; off <<= 1) {
            int t = (tid >= off) ? s_scan[tid - off] : 0;
            __syncthreads();
            acc += t;
            s_scan[tid] = acc;
            __syncthreads();
        }
        if (i < N_NODES) g_cursor[i] = g_scan_val[vt] + acc - v;
        __syncthreads();
    }
    grid_bar();

    // ---- phase 3: bin fill ----
    for (int e = gtid; e < N_EDGES; e += GSZ) {
        int sr = load_src(ei, e);
        int d  = load_dst(ei, e);
        if ((unsigned)sr >= N_NODES || (unsigned)d >= N_NODES) continue;
        int pos = atomicAdd(&g_cursor[d], 1);
        g_src_bin[pos] = sr;
    }
    grid_bar();   // last global sync: bins complete everywhere

    // ---- fused aggregate + GEMM per owned tile ----
    const int g  = wid >> 3;     // m-group: rows g*16..+15 (0..3)
    const int qn = wid & 7;      // n-eighth: cols qn*16..+15 (0..7)

    const int q = lane >> 3, r = lane & 7;
    const uint32_t aRel = (uint32_t)((g * 16 + (q & 1) * 8 + r) * GSTRIDE + (q >> 1) * 16);
    const uint32_t aHiA = sb + SM_AHI + aRel;
    const uint32_t aLoA = sb + SM_ALO + aRel;
    const uint32_t bRel = (uint32_t)((qn * 16 + (q >> 1) * 8 + r) * GSTRIDE + (q & 1) * 16);
    const uint32_t bHiA = sb + SM_BHI + bRel;
    const uint32_t bLoA = sb + SM_BLO + bRel;

    float2* out2 = (float2*)out4;
    const float* bs = (const float*)(smem + SM_BIAS);
    float* snorm = (float*)(smem + SM_NORM);   // [64 rows][8 slices]

    for (int tile = blockIdx.x; tile < NTILES; tile += COOP_GRID) {
        const int base = tile * GEMM_ROWS;

        // -- aggregate this tile's 64 nodes: warp w -> rows 2w, 2w+1;
        //    result written straight into smem A (k4 = 32+lane) as hi/lo --
        #pragma unroll
        for (int u = 0; u < 2; u++) {
            int rr = wid * 2 + u;
            int n  = base + rr;
            float4 a0 = make_float4(0.f, 0.f, 0.f, 0.f);
            float4 a1 = make_float4(0.f, 0.f, 0.f, 0.f);
            float4 a2 = make_float4(0.f, 0.f, 0.f, 0.f);
            float4 a3 = make_float4(0.f, 0.f, 0.f, 0.f);
            float sc = 0.f;
            if (n < N_NODES) {
                int end = g_cursor[n];
                int deg = g_deg_i[n];
                int beg = end - deg;
                for (int bb = beg; bb < end; bb += 32) {
                    int m = min(32, end - bb);
                    int sv = (bb + lane < end) ? __ldg(g_src_bin + bb + lane) : 0;
                    int j = 0;
                    for (; j + 3 < m; j += 4) {
                        int s0 = __shfl_sync(0xffffffffu, sv, j);
                        int s1 = __shfl_sync(0xffffffffu, sv, j + 1);
                        int s2 = __shfl_sync(0xffffffffu, sv, j + 2);
                        int s3 = __shfl_sync(0xffffffffu, sv, j + 3);
                        float4 v0 = __ldg(x4 + s0 * 32 + lane);
                        float4 v1 = __ldg(x4 + s1 * 32 + lane);
                        float4 v2 = __ldg(x4 + s2 * 32 + lane);
                        float4 v3 = __ldg(x4 + s3 * 32 + lane);
                        a0.x += v0.x; a0.y += v0.y; a0.z += v0.z; a0.w += v0.w;
                        a1.x += v1.x; a1.y += v1.y; a1.z += v1.z; a1.w += v1.w;
                        a2.x += v2.x; a2.y += v2.y; a2.z += v2.z; a2.w += v2.w;
                        a3.x += v3.x; a3.y += v3.y; a3.z += v3.z; a3.w += v3.w;
                    }
                    for (; j < m; j++) {
                        int s0 = __shfl_sync(0xffffffffu, sv, j);
                        float4 v0 = __ldg(x4 + s0 * 32 + lane);
                        a0.x += v0.x; a0.y += v0.y; a0.z += v0.z; a0.w += v0.w;
                    }
                }
                sc = 1.0f / fmaxf((float)deg, 1.0f);
            }
            float4 res = make_float4(((a0.x + a1.x) + (a2.x + a3.x)) * sc,
                                     ((a0.y + a1.y) + (a2.y + a3.y)) * sc,
                                     ((a0.z + a1.z) + (a2.z + a3.z)) * sc,
                                     ((a0.w + a1.w) + (a2.w + a3.w)) * sc);
            uint32_t off = (uint32_t)(rr * GSTRIDE + (32 + lane) * 8);
            *reinterpret_cast<uint2*>(smem + SM_AHI + off) = cvt_hi4(res);
            *reinterpret_cast<uint2*>(smem + SM_ALO + off) = cvt_lo4(res);
        }

        // -- stage x half (k4 0..31): 2048 float4 over 1024 threads --
        for (int i = tid; i < 2048; i += THREADS) {
            int rr = i >> 5, k4 = i & 31;
            int row = base + rr;
            float4 v = make_float4(0.f, 0.f, 0.f, 0.f);
            if (row < N_NODES) v = __ldg(x4 + row * 32 + k4);
            uint32_t off = (uint32_t)(rr * GSTRIDE + k4 * 8);
            *reinterpret_cast<uint2*>(smem + SM_AHI + off) = cvt_hi4(v);
            *reinterpret_cast<uint2*>(smem + SM_ALO + off) = cvt_lo4(v);
        }
        __syncthreads();

        // -- bf16-split MMA mainloop (3 interleaved passes) --
        float c[2][4];
        #pragma unroll
        for (int nt = 0; nt < 2; nt++)
            #pragma unroll
            for (int j = 0; j < 4; j++) c[nt][j] = 0.f;

        #pragma unroll 4
        for (int k = 0; k < 16; k++) {
            uint32_t ah[4], al[4], bh[2][2], bl[2][2];
            ldsm_x4(ah[0], ah[1], ah[2], ah[3], aHiA + k * 32);
            ldsm_x4(al[0], al[1], al[2], al[3], aLoA + k * 32);
            ldsm_x4(bh[0][0], bh[0][1], bh[1][0], bh[1][1], bHiA + k * 32);
            ldsm_x4(bl[0][0], bl[0][1], bl[1][0], bl[1][1], bLoA + k * 32);
            #pragma unroll
            for (int nt = 0; nt < 2; nt++) {
                mma_bf16(c[nt], ah, bh[nt]);
                mma_bf16(c[nt], ah, bl[nt]);
                mma_bf16(c[nt], al, bh[nt]);
            }
        }

        // -- epilogue 1: per-slice partial row norms -> smem --
        #pragma unroll
        for (int h2 = 0; h2 < 2; h2++) {
            float ss = 0.f;
            #pragma unroll
            for (int nt = 0; nt < 2; nt++) {
                int col = qn * 16 + nt * 8 + (lane & 3) * 2;
                float v0 = c[nt][2*h2 + 0] + bs[col + 0];
                float v1 = c[nt][2*h2 + 1] + bs[col + 1];
                ss += v0 * v0 + v1 * v1;
            }
            ss += __shfl_xor_sync(0xffffffffu, ss, 1);
            ss += __shfl_xor_sync(0xffffffffu, ss, 2);
            if ((lane & 3) == 0)
                snorm[(g * 16 + h2 * 8 + (lane >> 2)) * 8 + qn] = ss;
        }
        __syncthreads();

        // -- epilogue 2: combine slices, normalize, store --
        #pragma unroll
        for (int h2 = 0; h2 < 2; h2++) {
            int rl = g * 16 + h2 * 8 + (lane >> 2);
            float ss = ((snorm[rl*8+0] + snorm[rl*8+1]) + (snorm[rl*8+2] + snorm[rl*8+3]))
                     + ((snorm[rl*8+4] + snorm[rl*8+5]) + (snorm[rl*8+6] + snorm[rl*8+7]));
            float sc = 1.0f / fmaxf(sqrtf(ss), 1e-12f);
            int row = base + rl;
            if (row < N_NODES) {
                #pragma unroll
                for (int nt = 0; nt < 2; nt++) {
                    int col = qn * 16 + nt * 8 + (lane & 3) * 2;
                    float v0 = c[nt][2*h2 + 0] + bs[col + 0];
                    float v1 = c[nt][2*h2 + 1] + bs[col + 1];
                    out2[row * 64 + qn * 8 + nt * 4 + (lane & 3)] =
                        make_float2(v0 * sc, v1 * sc);
                }
            }
        }
        __syncthreads();   // snorm/A reused next tile
    }
}

// ---------------------------------------------------------------------------
extern "C" void kernel_launch(void* const* d_in, const int* in_sizes, int n_in,
                              void* d_out, int out_size) {
    const float4*    x4   = (const float4*)d_in[0];
    const long long* ei   = (const long long*)d_in[1];
    const float4*    W4   = (const float4*)d_in[2];
    const float*     bias = (const float*)d_in[3];
    float4*          out4 = (float4*)d_out;

    cudaFuncSetAttribute(k_fused,
                         cudaFuncAttributeMaxDynamicSharedMemorySize, SM_TOT);

    k_fused<<<COOP_GRID, THREADS, SM_TOT>>>(ei, x4, W4, bias, out4);
}